// round 2
// baseline (speedup 1.0000x reference)
#include <cuda_runtime.h>
#include <cstdint>

#define N_NODES 50000
#define N_EDGES 600000
#define N_GRAPHS 1000
#define HID 128
#define NEG_SLOPE 0.01f

// ---------------- scratch (static device globals; no allocation) ----------------
__device__ float g_bufA[(size_t)N_NODES * HID];  // 25.6 MB
__device__ float g_bufB[(size_t)N_NODES * HID];  // 25.6 MB
__device__ float g_bufC[(size_t)N_NODES * HID];  // 25.6 MB
__device__ float g_deg[N_NODES];
__device__ float g_dinv[N_NODES];
__device__ float g_pool[N_GRAPHS * HID];
__device__ float g_cnt[N_GRAPHS];

// ---------------- helpers ----------------
__device__ __forceinline__ float leaky(float x) {
    return x > 0.0f ? x : NEG_SLOPE * x;
}

__device__ __forceinline__ void red_add_v4(float* addr, float a, float b, float c, float d) {
    asm volatile("red.global.add.v4.f32 [%0], {%1, %2, %3, %4};"
                 :: "l"(addr), "f"(a), "f"(b), "f"(c), "f"(d) : "memory");
}

// ---------------- zero scratch accumulators ----------------
__global__ void zero_kernel(float* deg, float* pool, float* cnt) {
    int i = blockIdx.x * blockDim.x + threadIdx.x;
    if (i < N_GRAPHS * HID) pool[i] = 0.0f;
    if (i < N_NODES) deg[i] = 0.0f;
    if (i < N_GRAPHS) cnt[i] = 0.0f;
}

// ---------------- degree over dst ----------------
__global__ void deg_kernel(const int* __restrict__ dst, float* __restrict__ deg) {
    int e = blockIdx.x * blockDim.x + threadIdx.x;
    if (e < N_EDGES) atomicAdd(&deg[dst[e]], 1.0f);
}

__global__ void dinv_kernel(const float* __restrict__ deg, float* __restrict__ dinv) {
    int i = blockIdx.x * blockDim.x + threadIdx.x;
    if (i < N_NODES) dinv[i] = rsqrtf(deg[i] + 1.0f);
}

// ---------------- fp32 GEMM: H = X*W ; AGG = H * dinv^2 (self-loop init) ----------------
// BM=128, BN=128(=HID), BK=32, 256 threads, 8x8 register tile per thread.
__global__ __launch_bounds__(256) void gemm_kernel(
    const float* __restrict__ X, const float* __restrict__ W,
    float* __restrict__ H, float* __restrict__ AGG,
    const float* __restrict__ dinv, int M)
{
    __shared__ float Xs[32][132];   // k-major, padded (132*4 = 528 B, 16B-aligned rows)
    __shared__ float Ws[32][128];

    const int tid = threadIdx.x;
    const int tx = tid & 15;        // 0..15 -> 8 cols each
    const int ty = tid >> 4;        // 0..15 -> 8 rows each
    const int rowBase = blockIdx.x * 128;

    float acc[8][8];
#pragma unroll
    for (int i = 0; i < 8; i++)
#pragma unroll
        for (int j = 0; j < 8; j++) acc[i][j] = 0.0f;

    for (int k0 = 0; k0 < HID; k0 += 32) {
        // load X tile (128 rows x 32 k) transposed into Xs[k][row]
#pragma unroll
        for (int l = 0; l < 4; l++) {
            int idx = tid + l * 256;       // float4 index, 0..1023
            int r   = idx >> 3;            // row within tile
            int k4  = idx & 7;             // float4 within row
            int gr  = rowBase + r;
            float4 v = make_float4(0.f, 0.f, 0.f, 0.f);
            if (gr < M)
                v = *(const float4*)(X + (size_t)gr * HID + k0 + k4 * 4);
            Xs[k4 * 4 + 0][r] = v.x;
            Xs[k4 * 4 + 1][r] = v.y;
            Xs[k4 * 4 + 2][r] = v.z;
            Xs[k4 * 4 + 3][r] = v.w;
        }
        // load W tile (32 k x 128 cols)
#pragma unroll
        for (int l = 0; l < 4; l++) {
            int idx = tid + l * 256;       // float4 index, 0..1023
            int kr  = idx >> 5;            // k row
            int c4  = idx & 31;            // float4 col
            float4 v = *(const float4*)(W + (size_t)(k0 + kr) * HID + c4 * 4);
            *(float4*)&Ws[kr][c4 * 4] = v;
        }
        __syncthreads();

#pragma unroll
        for (int k = 0; k < 32; k++) {
            float4 x0 = *(const float4*)&Xs[k][ty * 8];
            float4 x1 = *(const float4*)&Xs[k][ty * 8 + 4];
            float4 w0 = *(const float4*)&Ws[k][tx * 8];
            float4 w1 = *(const float4*)&Ws[k][tx * 8 + 4];
            float xr[8] = {x0.x, x0.y, x0.z, x0.w, x1.x, x1.y, x1.z, x1.w};
            float wr[8] = {w0.x, w0.y, w0.z, w0.w, w1.x, w1.y, w1.z, w1.w};
#pragma unroll
            for (int i = 0; i < 8; i++)
#pragma unroll
                for (int j = 0; j < 8; j++)
                    acc[i][j] = fmaf(xr[i], wr[j], acc[i][j]);
        }
        __syncthreads();
    }

    // epilogue: write H and AGG = H*dinv^2
#pragma unroll
    for (int i = 0; i < 8; i++) {
        int r = rowBase + ty * 8 + i;
        if (r >= M) break;
        float di = dinv[r];
        float s = di * di;
        size_t base = (size_t)r * HID + tx * 8;
        float4 h0 = make_float4(acc[i][0], acc[i][1], acc[i][2], acc[i][3]);
        float4 h1 = make_float4(acc[i][4], acc[i][5], acc[i][6], acc[i][7]);
        *(float4*)(H + base)     = h0;
        *(float4*)(H + base + 4) = h1;
        float4 a0 = make_float4(h0.x * s, h0.y * s, h0.z * s, h0.w * s);
        float4 a1 = make_float4(h1.x * s, h1.y * s, h1.z * s, h1.w * s);
        *(float4*)(AGG + base)     = a0;
        *(float4*)(AGG + base + 4) = a1;
    }
}

// ---------------- edge scatter: AGG[dst] += H[src] * dinv[src]*dinv[dst] ----------------
// one warp per edge; one red.v4 per lane
__global__ __launch_bounds__(256) void scatter_kernel(
    const float* __restrict__ H, float* __restrict__ AGG,
    const int* __restrict__ src, const int* __restrict__ dst,
    const float* __restrict__ dinv)
{
    int t = blockIdx.x * blockDim.x + threadIdx.x;
    int e = t >> 5;
    int lane = t & 31;
    if (e >= N_EDGES) return;
    int s = __ldg(src + e);
    int d = __ldg(dst + e);
    float c = __ldg(dinv + s) * __ldg(dinv + d);
    float4 v = *(const float4*)(H + (size_t)s * HID + lane * 4);
    float* addr = AGG + (size_t)d * HID + lane * 4;
    red_add_v4(addr, v.x * c, v.y * c, v.z * c, v.w * c);
}

// ---------------- activation: OUT = leaky(IN + bias) ----------------
__global__ void act_kernel(const float* __restrict__ IN, const float* __restrict__ bias,
                           float* __restrict__ OUT)
{
    int i = blockIdx.x * blockDim.x + threadIdx.x;   // float4 index
    const int total = N_NODES * HID / 4;
    if (i >= total) return;
    int c4 = i & 31;
    float4 b = *(const float4*)(bias + c4 * 4);
    float4 v = *(const float4*)(IN + (size_t)i * 4);
    v.x = leaky(v.x + b.x);
    v.y = leaky(v.y + b.y);
    v.z = leaky(v.z + b.z);
    v.w = leaky(v.w + b.w);
    *(float4*)(OUT + (size_t)i * 4) = v;
}

// ---------------- pool: for each node, leaky(IN+b2) accumulated into pool[batch[n]] ----------------
__global__ __launch_bounds__(256) void pool_kernel(
    const float* __restrict__ IN, const float* __restrict__ bias,
    const int* __restrict__ batch, float* __restrict__ pool, float* __restrict__ cnt)
{
    int t = blockIdx.x * blockDim.x + threadIdx.x;
    int n = t >> 5;
    int lane = t & 31;
    if (n >= N_NODES) return;
    int g = __ldg(batch + n);
    float4 b = *(const float4*)(bias + lane * 4);
    float4 v = *(const float4*)(IN + (size_t)n * HID + lane * 4);
    v.x = leaky(v.x + b.x);
    v.y = leaky(v.y + b.y);
    v.z = leaky(v.z + b.z);
    v.w = leaky(v.w + b.w);
    red_add_v4(pool + (size_t)g * HID + lane * 4, v.x, v.y, v.z, v.w);
    if (lane == 0) atomicAdd(&cnt[g], 1.0f);
}

// ---------------- finalize: out = pool / max(cnt,1) ----------------
__global__ void finalize_kernel(const float* __restrict__ pool, const float* __restrict__ cnt,
                                float* __restrict__ out)
{
    int i = blockIdx.x * blockDim.x + threadIdx.x;
    if (i >= N_GRAPHS * HID) return;
    int g = i >> 7;
    out[i] = pool[i] / fmaxf(cnt[g], 1.0f);
}

// ---------------- launch ----------------
extern "C" void kernel_launch(void* const* d_in, const int* in_sizes, int n_in,
                              void* d_out, int out_size)
{
    const float* drug_x = (const float*)d_in[0];   // [50000,128]
    const float* W1     = (const float*)d_in[1];   // [128,128]
    const float* b1     = (const float*)d_in[2];   // [128]
    const float* W2     = (const float*)d_in[3];   // [128,128]
    const float* b2     = (const float*)d_in[4];   // [128]
    const int*   eidx   = (const int*)d_in[5];     // [2,600000]
    const int*   batch  = (const int*)d_in[6];     // [50000]
    float* out = (float*)d_out;

    const int* src = eidx;
    const int* dst = eidx + N_EDGES;

    float *bufA, *bufB, *bufC, *deg, *dinv, *pool, *cnt;
    cudaGetSymbolAddress((void**)&bufA, g_bufA);
    cudaGetSymbolAddress((void**)&bufB, g_bufB);
    cudaGetSymbolAddress((void**)&bufC, g_bufC);
    cudaGetSymbolAddress((void**)&deg,  g_deg);
    cudaGetSymbolAddress((void**)&dinv, g_dinv);
    cudaGetSymbolAddress((void**)&pool, g_pool);
    cudaGetSymbolAddress((void**)&cnt,  g_cnt);

    const int T = 256;
    int gemm_blocks = (N_NODES + 127) / 128;               // 391
    int scat_blocks = (N_EDGES * 32 + T - 1) / T;          // 75000
    int act_blocks  = (N_NODES * HID / 4 + T - 1) / T;     // 6250
    int poolb       = (N_NODES * 32 + T - 1) / T;          // 6250

    zero_kernel<<<(N_GRAPHS * HID + T - 1) / T, T>>>(deg, pool, cnt);
    deg_kernel<<<(N_EDGES + T - 1) / T, T>>>(dst, deg);
    dinv_kernel<<<(N_NODES + T - 1) / T, T>>>(deg, dinv);

    // layer 1
    gemm_kernel<<<gemm_blocks, T>>>(drug_x, W1, bufA, bufB, dinv, N_NODES);
    scatter_kernel<<<scat_blocks, T>>>(bufA, bufB, src, dst, dinv);
    act_kernel<<<act_blocks, T>>>(bufB, b1, bufC);

    // layer 2
    gemm_kernel<<<gemm_blocks, T>>>(bufC, W2, bufA, bufB, dinv, N_NODES);
    scatter_kernel<<<scat_blocks, T>>>(bufA, bufB, src, dst, dinv);

    // pool (fuses bias2 + leaky) and finalize
    pool_kernel<<<poolb, T>>>(bufB, b2, batch, pool, cnt);
    finalize_kernel<<<(N_GRAPHS * HID + T - 1) / T, T>>>(pool, cnt, out);
}

// round 3
// speedup vs baseline: 1.0833x; 1.0833x over previous
#include <cuda_runtime.h>
#include <cstdint>

#define N_NODES 50000
#define N_EDGES 600000
#define N_GRAPHS 1000
#define HID 128
#define NEG_SLOPE 0.01f

// ---------------- scratch (static device globals; no allocation) ----------------
__device__ float g_bufA[(size_t)N_NODES * HID];  // 25.6 MB  (H)
__device__ float g_bufB[(size_t)N_NODES * HID];  // 25.6 MB
__device__ float g_bufC[(size_t)N_NODES * HID];  // 25.6 MB
__device__ float g_dinv[N_NODES];
__device__ float g_pool[N_GRAPHS * HID];
__device__ float g_cnt[N_GRAPHS];
__device__ int   g_count[N_NODES];
__device__ int   g_rowptr[N_NODES + 1];
__device__ int   g_cursor[N_NODES];
__device__ int   g_csr_src[N_EDGES];
__device__ float g_csr_coef[N_EDGES];

// ---------------- helpers ----------------
__device__ __forceinline__ float leaky(float x) {
    return x > 0.0f ? x : NEG_SLOPE * x;
}

__device__ __forceinline__ void red_add_v4(float* addr, float a, float b, float c, float d) {
    asm volatile("red.global.add.v4.f32 [%0], {%1, %2, %3, %4};"
                 :: "l"(addr), "f"(a), "f"(b), "f"(c), "f"(d) : "memory");
}

// ---------------- init: zero pool/cnt/count ----------------
__global__ void init_kernel(float* pool, float* cnt, int* count) {
    int i = blockIdx.x * blockDim.x + threadIdx.x;
    if (i < N_GRAPHS * HID) pool[i] = 0.0f;
    if (i < N_NODES) count[i] = 0;
    if (i < N_GRAPHS) cnt[i] = 0.0f;
}

// ---------------- degree histogram over dst (int) ----------------
__global__ void hist_kernel(const int* __restrict__ dst, int* __restrict__ count) {
    int e = blockIdx.x * blockDim.x + threadIdx.x;
    if (e < N_EDGES) atomicAdd(&count[dst[e]], 1);
}

__global__ void dinv_kernel(const int* __restrict__ count, float* __restrict__ dinv) {
    int i = blockIdx.x * blockDim.x + threadIdx.x;
    if (i < N_NODES) dinv[i] = rsqrtf((float)count[i] + 1.0f);
}

// ---------------- single-block exclusive scan -> rowptr, cursor ----------------
__global__ __launch_bounds__(1024) void scan_kernel(const int* __restrict__ count,
                                                    int* __restrict__ rowptr,
                                                    int* __restrict__ cursor)
{
    __shared__ int sums[1024];
    const int t = threadIdx.x;
    const int CH = (N_NODES + 1023) / 1024;  // 49
    int beg = t * CH;
    int end = min(beg + CH, N_NODES);
    int s = 0;
    for (int i = beg; i < end; i++) s += count[i];
    sums[t] = s;
    __syncthreads();
    // inclusive Hillis-Steele scan
    for (int off = 1; off < 1024; off <<= 1) {
        int v = (t >= off) ? sums[t - off] : 0;
        __syncthreads();
        sums[t] += v;
        __syncthreads();
    }
    int run = (t > 0) ? sums[t - 1] : 0;  // exclusive prefix of this chunk
    for (int i = beg; i < end; i++) {
        rowptr[i] = run;
        cursor[i] = run;
        run += count[i];
    }
    if (t == 1023) rowptr[N_NODES] = run;
}

// ---------------- fill CSR: src idx + precomputed coef ----------------
__global__ void fill_kernel(const int* __restrict__ src, const int* __restrict__ dst,
                            const float* __restrict__ dinv, int* __restrict__ cursor,
                            int* __restrict__ csr_src, float* __restrict__ csr_coef)
{
    int e = blockIdx.x * blockDim.x + threadIdx.x;
    if (e >= N_EDGES) return;
    int s = __ldg(src + e);
    int d = __ldg(dst + e);
    int p = atomicAdd(&cursor[d], 1);
    csr_src[p] = s;
    csr_coef[p] = __ldg(dinv + s) * __ldg(dinv + d);
}

// ---------------- fp32 GEMM: H = X*W ----------------
// BM=128, BN=128(=HID), BK=32, 256 threads, 8x8 register tile per thread.
__global__ __launch_bounds__(256) void gemm_kernel(
    const float* __restrict__ X, const float* __restrict__ W,
    float* __restrict__ H, int M)
{
    __shared__ float Xs[32][132];
    __shared__ float Ws[32][128];

    const int tid = threadIdx.x;
    const int tx = tid & 15;
    const int ty = tid >> 4;
    const int rowBase = blockIdx.x * 128;

    float acc[8][8];
#pragma unroll
    for (int i = 0; i < 8; i++)
#pragma unroll
        for (int j = 0; j < 8; j++) acc[i][j] = 0.0f;

    for (int k0 = 0; k0 < HID; k0 += 32) {
#pragma unroll
        for (int l = 0; l < 4; l++) {
            int idx = tid + l * 256;
            int r   = idx >> 3;
            int k4  = idx & 7;
            int gr  = rowBase + r;
            float4 v = make_float4(0.f, 0.f, 0.f, 0.f);
            if (gr < M)
                v = *(const float4*)(X + (size_t)gr * HID + k0 + k4 * 4);
            Xs[k4 * 4 + 0][r] = v.x;
            Xs[k4 * 4 + 1][r] = v.y;
            Xs[k4 * 4 + 2][r] = v.z;
            Xs[k4 * 4 + 3][r] = v.w;
        }
#pragma unroll
        for (int l = 0; l < 4; l++) {
            int idx = tid + l * 256;
            int kr  = idx >> 5;
            int c4  = idx & 31;
            float4 v = *(const float4*)(W + (size_t)(k0 + kr) * HID + c4 * 4);
            *(float4*)&Ws[kr][c4 * 4] = v;
        }
        __syncthreads();

#pragma unroll
        for (int k = 0; k < 32; k++) {
            float4 x0 = *(const float4*)&Xs[k][ty * 8];
            float4 x1 = *(const float4*)&Xs[k][ty * 8 + 4];
            float4 w0 = *(const float4*)&Ws[k][tx * 8];
            float4 w1 = *(const float4*)&Ws[k][tx * 8 + 4];
            float xr[8] = {x0.x, x0.y, x0.z, x0.w, x1.x, x1.y, x1.z, x1.w};
            float wr[8] = {w0.x, w0.y, w0.z, w0.w, w1.x, w1.y, w1.z, w1.w};
#pragma unroll
            for (int i = 0; i < 8; i++)
#pragma unroll
                for (int j = 0; j < 8; j++)
                    acc[i][j] = fmaf(xr[i], wr[j], acc[i][j]);
        }
        __syncthreads();
    }

#pragma unroll
    for (int i = 0; i < 8; i++) {
        int r = rowBase + ty * 8 + i;
        if (r >= M) break;
        size_t base = (size_t)r * HID + tx * 8;
        *(float4*)(H + base)     = make_float4(acc[i][0], acc[i][1], acc[i][2], acc[i][3]);
        *(float4*)(H + base + 4) = make_float4(acc[i][4], acc[i][5], acc[i][6], acc[i][7]);
    }
}

// ---------------- gather aggregation + bias + leaky ----------------
// one warp per dst node; OUT = leaky( sum_e coef*H[src] + dinv^2*H[n] + bias )
__global__ __launch_bounds__(256) void gather_kernel(
    const float* __restrict__ H, float* __restrict__ OUT,
    const int* __restrict__ rowptr, const int* __restrict__ csr_src,
    const float* __restrict__ csr_coef, const float* __restrict__ dinv,
    const float* __restrict__ bias)
{
    int n = blockIdx.x * 8 + (threadIdx.x >> 5);
    int lane = threadIdx.x & 31;
    if (n >= N_NODES) return;

    float di = __ldg(dinv + n);
    float sl = di * di;
    float4 a = *(const float4*)(H + (size_t)n * HID + lane * 4);
    float4 acc = make_float4(a.x * sl, a.y * sl, a.z * sl, a.w * sl);

    int i   = __ldg(rowptr + n);
    int end = __ldg(rowptr + n + 1);

    // 4-way unroll for memory-level parallelism
    for (; i + 4 <= end; i += 4) {
        int s0 = __ldg(csr_src + i + 0);
        int s1 = __ldg(csr_src + i + 1);
        int s2 = __ldg(csr_src + i + 2);
        int s3 = __ldg(csr_src + i + 3);
        float c0 = __ldg(csr_coef + i + 0);
        float c1 = __ldg(csr_coef + i + 1);
        float c2 = __ldg(csr_coef + i + 2);
        float c3 = __ldg(csr_coef + i + 3);
        float4 v0 = *(const float4*)(H + (size_t)s0 * HID + lane * 4);
        float4 v1 = *(const float4*)(H + (size_t)s1 * HID + lane * 4);
        float4 v2 = *(const float4*)(H + (size_t)s2 * HID + lane * 4);
        float4 v3 = *(const float4*)(H + (size_t)s3 * HID + lane * 4);
        acc.x = fmaf(c0, v0.x, acc.x); acc.y = fmaf(c0, v0.y, acc.y);
        acc.z = fmaf(c0, v0.z, acc.z); acc.w = fmaf(c0, v0.w, acc.w);
        acc.x = fmaf(c1, v1.x, acc.x); acc.y = fmaf(c1, v1.y, acc.y);
        acc.z = fmaf(c1, v1.z, acc.z); acc.w = fmaf(c1, v1.w, acc.w);
        acc.x = fmaf(c2, v2.x, acc.x); acc.y = fmaf(c2, v2.y, acc.y);
        acc.z = fmaf(c2, v2.z, acc.z); acc.w = fmaf(c2, v2.w, acc.w);
        acc.x = fmaf(c3, v3.x, acc.x); acc.y = fmaf(c3, v3.y, acc.y);
        acc.z = fmaf(c3, v3.z, acc.z); acc.w = fmaf(c3, v3.w, acc.w);
    }
    for (; i < end; i++) {
        int s = __ldg(csr_src + i);
        float c = __ldg(csr_coef + i);
        float4 v = *(const float4*)(H + (size_t)s * HID + lane * 4);
        acc.x = fmaf(c, v.x, acc.x); acc.y = fmaf(c, v.y, acc.y);
        acc.z = fmaf(c, v.z, acc.z); acc.w = fmaf(c, v.w, acc.w);
    }

    float4 b = *(const float4*)(bias + lane * 4);
    acc.x = leaky(acc.x + b.x);
    acc.y = leaky(acc.y + b.y);
    acc.z = leaky(acc.z + b.z);
    acc.w = leaky(acc.w + b.w);
    *(float4*)(OUT + (size_t)n * HID + lane * 4) = acc;
}

// ---------------- pool: accumulate IN (already activated) into pool[batch[n]] ----------------
__global__ __launch_bounds__(256) void pool_kernel(
    const float* __restrict__ IN, const int* __restrict__ batch,
    float* __restrict__ pool, float* __restrict__ cnt)
{
    int t = blockIdx.x * blockDim.x + threadIdx.x;
    int n = t >> 5;
    int lane = t & 31;
    if (n >= N_NODES) return;
    int g = __ldg(batch + n);
    float4 v = *(const float4*)(IN + (size_t)n * HID + lane * 4);
    red_add_v4(pool + (size_t)g * HID + lane * 4, v.x, v.y, v.z, v.w);
    if (lane == 0) atomicAdd(&cnt[g], 1.0f);
}

// ---------------- finalize ----------------
__global__ void finalize_kernel(const float* __restrict__ pool, const float* __restrict__ cnt,
                                float* __restrict__ out)
{
    int i = blockIdx.x * blockDim.x + threadIdx.x;
    if (i >= N_GRAPHS * HID) return;
    int g = i >> 7;
    out[i] = pool[i] / fmaxf(cnt[g], 1.0f);
}

// ---------------- launch ----------------
extern "C" void kernel_launch(void* const* d_in, const int* in_sizes, int n_in,
                              void* d_out, int out_size)
{
    const float* drug_x = (const float*)d_in[0];
    const float* W1     = (const float*)d_in[1];
    const float* b1     = (const float*)d_in[2];
    const float* W2     = (const float*)d_in[3];
    const float* b2     = (const float*)d_in[4];
    const int*   eidx   = (const int*)d_in[5];
    const int*   batch  = (const int*)d_in[6];
    float* out = (float*)d_out;

    const int* src = eidx;
    const int* dst = eidx + N_EDGES;

    float *bufA, *bufB, *bufC, *dinv, *pool, *cnt, *csr_coef;
    int *count, *rowptr, *cursor, *csr_src;
    cudaGetSymbolAddress((void**)&bufA, g_bufA);
    cudaGetSymbolAddress((void**)&bufB, g_bufB);
    cudaGetSymbolAddress((void**)&bufC, g_bufC);
    cudaGetSymbolAddress((void**)&dinv, g_dinv);
    cudaGetSymbolAddress((void**)&pool, g_pool);
    cudaGetSymbolAddress((void**)&cnt,  g_cnt);
    cudaGetSymbolAddress((void**)&count,  g_count);
    cudaGetSymbolAddress((void**)&rowptr, g_rowptr);
    cudaGetSymbolAddress((void**)&cursor, g_cursor);
    cudaGetSymbolAddress((void**)&csr_src,  g_csr_src);
    cudaGetSymbolAddress((void**)&csr_coef, g_csr_coef);

    const int T = 256;
    int gemm_blocks = (N_NODES + 127) / 128;           // 391
    int gath_blocks = (N_NODES + 7) / 8;               // 6250
    int poolb       = (N_NODES * 32 + T - 1) / T;      // 6250

    // CSR build (reused by both layers)
    init_kernel<<<(N_GRAPHS * HID + T - 1) / T, T>>>(pool, cnt, count);
    hist_kernel<<<(N_EDGES + T - 1) / T, T>>>(dst, count);
    dinv_kernel<<<(N_NODES + T - 1) / T, T>>>(count, dinv);
    scan_kernel<<<1, 1024>>>(count, rowptr, cursor);
    fill_kernel<<<(N_EDGES + T - 1) / T, T>>>(src, dst, dinv, cursor, csr_src, csr_coef);

    // layer 1:  bufA = X*W1 ;  bufC = leaky(aggregate(bufA) + b1)
    gemm_kernel<<<gemm_blocks, T>>>(drug_x, W1, bufA, N_NODES);
    gather_kernel<<<gath_blocks, T>>>(bufA, bufC, rowptr, csr_src, csr_coef, dinv, b1);

    // layer 2:  bufA = bufC*W2 ;  bufB = leaky(aggregate(bufA) + b2)
    gemm_kernel<<<gemm_blocks, T>>>(bufC, W2, bufA, N_NODES);
    gather_kernel<<<gath_blocks, T>>>(bufA, bufB, rowptr, csr_src, csr_coef, dinv, b2);

    // mean pool
    pool_kernel<<<poolb, T>>>(bufB, batch, pool, cnt);
    finalize_kernel<<<(N_GRAPHS * HID + T - 1) / T, T>>>(pool, cnt, out);
}

// round 4
// speedup vs baseline: 1.4596x; 1.3474x over previous
#include <cuda_runtime.h>
#include <cstdint>

#define N_NODES 50000
#define N_EDGES 600000
#define N_GRAPHS 1000
#define HID 128
#define NEG_SLOPE 0.01f

#define SCAN_T 256
#define SCAN_B ((N_NODES + SCAN_T - 1) / SCAN_T)   // 196

// ---------------- scratch (static device globals; no allocation) ----------------
__device__ float g_bufA[(size_t)N_NODES * HID];
__device__ float g_bufB[(size_t)N_NODES * HID];
__device__ float g_bufC[(size_t)N_NODES * HID];
__device__ float g_dinv[N_NODES];
__device__ float g_pool[N_GRAPHS * HID];
__device__ float g_cnt[N_GRAPHS];
__device__ int   g_count[N_NODES];
__device__ int   g_rowptr[N_NODES + 1];
__device__ int   g_cursor[N_NODES];
__device__ int   g_csr_src[N_EDGES];
__device__ float g_csr_coef[N_EDGES];
__device__ int   g_blocksum[SCAN_B];
__device__ int   g_blockoff[SCAN_B];

// ---------------- helpers ----------------
__device__ __forceinline__ float leaky(float x) {
    return x > 0.0f ? x : NEG_SLOPE * x;
}

__device__ __forceinline__ void red_add_v4(float* addr, float a, float b, float c, float d) {
    asm volatile("red.global.add.v4.f32 [%0], {%1, %2, %3, %4};"
                 :: "l"(addr), "f"(a), "f"(b), "f"(c), "f"(d) : "memory");
}

// ---------------- init: zero pool/cnt/count ----------------
__global__ void init_kernel(float* pool, float* cnt, int* count) {
    int i = blockIdx.x * blockDim.x + threadIdx.x;
    if (i < N_GRAPHS * HID) pool[i] = 0.0f;
    if (i < N_NODES) count[i] = 0;
    if (i < N_GRAPHS) cnt[i] = 0.0f;
}

// ---------------- degree histogram over dst (int) ----------------
__global__ void hist_kernel(const int* __restrict__ dst, int* __restrict__ count) {
    int e = blockIdx.x * blockDim.x + threadIdx.x;
    if (e < N_EDGES) atomicAdd(&count[dst[e]], 1);
}

__global__ void dinv_kernel(const int* __restrict__ count, float* __restrict__ dinv) {
    int i = blockIdx.x * blockDim.x + threadIdx.x;
    if (i < N_NODES) dinv[i] = rsqrtf((float)count[i] + 1.0f);
}

// ---------------- scan phase 1: per-block sums ----------------
__global__ __launch_bounds__(SCAN_T) void blocksum_kernel(const int* __restrict__ count,
                                                          int* __restrict__ blocksum)
{
    __shared__ int warpsum[SCAN_T / 32];
    int i = blockIdx.x * SCAN_T + threadIdx.x;
    int v = (i < N_NODES) ? count[i] : 0;
#pragma unroll
    for (int off = 16; off > 0; off >>= 1)
        v += __shfl_down_sync(0xffffffffu, v, off);
    if ((threadIdx.x & 31) == 0) warpsum[threadIdx.x >> 5] = v;
    __syncthreads();
    if (threadIdx.x < SCAN_T / 32) {
        int s = warpsum[threadIdx.x];
#pragma unroll
        for (int off = SCAN_T / 64; off > 0; off >>= 1)
            s += __shfl_down_sync(0xffu, s, off);
        if (threadIdx.x == 0) blocksum[blockIdx.x] = s;
    }
}

// ---------------- scan phase 2: exclusive scan of block sums (1 block) ----------------
__global__ __launch_bounds__(256) void scanblock_kernel(const int* __restrict__ blocksum,
                                                        int* __restrict__ blockoff)
{
    __shared__ int warptot[8];
    int t = threadIdx.x;
    int v = (t < SCAN_B) ? blocksum[t] : 0;
    int lane = t & 31, w = t >> 5;
    // warp inclusive scan
    int x = v;
#pragma unroll
    for (int off = 1; off < 32; off <<= 1) {
        int y = __shfl_up_sync(0xffffffffu, x, off);
        if (lane >= off) x += y;
    }
    if (lane == 31) warptot[w] = x;
    __syncthreads();
    if (t < 8) {
        int s = warptot[t];
#pragma unroll
        for (int off = 1; off < 8; off <<= 1) {
            int y = __shfl_up_sync(0xffu, s, off);
            if (t >= off) s += y;
        }
        warptot[t] = s;
    }
    __syncthreads();
    int excl = x - v + (w > 0 ? warptot[w - 1] : 0);
    if (t < SCAN_B) blockoff[t] = excl;
}

// ---------------- scan phase 3: block-local exclusive scan + offset -> rowptr/cursor ----------------
__global__ __launch_bounds__(SCAN_T) void writeptr_kernel(const int* __restrict__ count,
                                                          const int* __restrict__ blockoff,
                                                          int* __restrict__ rowptr,
                                                          int* __restrict__ cursor)
{
    __shared__ int warptot[SCAN_T / 32];
    int i = blockIdx.x * SCAN_T + threadIdx.x;
    int v = (i < N_NODES) ? count[i] : 0;
    int lane = threadIdx.x & 31, w = threadIdx.x >> 5;
    int x = v;
#pragma unroll
    for (int off = 1; off < 32; off <<= 1) {
        int y = __shfl_up_sync(0xffffffffu, x, off);
        if (lane >= off) x += y;
    }
    if (lane == 31) warptot[w] = x;
    __syncthreads();
    if (threadIdx.x < SCAN_T / 32) {
        int s = warptot[threadIdx.x];
#pragma unroll
        for (int off = 1; off < SCAN_T / 32; off <<= 1) {
            int y = __shfl_up_sync(0xffu, s, off);
            if ((int)threadIdx.x >= off) s += y;
        }
        warptot[threadIdx.x] = s;
    }
    __syncthreads();
    int excl = x - v + (w > 0 ? warptot[w - 1] : 0) + blockoff[blockIdx.x];
    if (i < N_NODES) {
        rowptr[i] = excl;
        cursor[i] = excl;
    }
    if (i == 0) rowptr[N_NODES] = N_EDGES;
}

// ---------------- fill CSR: src idx + precomputed coef ----------------
__global__ void fill_kernel(const int* __restrict__ src, const int* __restrict__ dst,
                            const float* __restrict__ dinv, int* __restrict__ cursor,
                            int* __restrict__ csr_src, float* __restrict__ csr_coef)
{
    int e = blockIdx.x * blockDim.x + threadIdx.x;
    if (e >= N_EDGES) return;
    int s = __ldg(src + e);
    int d = __ldg(dst + e);
    int p = atomicAdd(&cursor[d], 1);
    csr_src[p] = s;
    csr_coef[p] = __ldg(dinv + s) * __ldg(dinv + d);
}

// ---------------- fp32 GEMM: H = X*W ----------------
__global__ __launch_bounds__(256) void gemm_kernel(
    const float* __restrict__ X, const float* __restrict__ W,
    float* __restrict__ H, int M)
{
    __shared__ float Xs[32][132];
    __shared__ float Ws[32][128];

    const int tid = threadIdx.x;
    const int tx = tid & 15;
    const int ty = tid >> 4;
    const int rowBase = blockIdx.x * 128;

    float acc[8][8];
#pragma unroll
    for (int i = 0; i < 8; i++)
#pragma unroll
        for (int j = 0; j < 8; j++) acc[i][j] = 0.0f;

    for (int k0 = 0; k0 < HID; k0 += 32) {
#pragma unroll
        for (int l = 0; l < 4; l++) {
            int idx = tid + l * 256;
            int r   = idx >> 3;
            int k4  = idx & 7;
            int gr  = rowBase + r;
            float4 v = make_float4(0.f, 0.f, 0.f, 0.f);
            if (gr < M)
                v = *(const float4*)(X + (size_t)gr * HID + k0 + k4 * 4);
            Xs[k4 * 4 + 0][r] = v.x;
            Xs[k4 * 4 + 1][r] = v.y;
            Xs[k4 * 4 + 2][r] = v.z;
            Xs[k4 * 4 + 3][r] = v.w;
        }
#pragma unroll
        for (int l = 0; l < 4; l++) {
            int idx = tid + l * 256;
            int kr  = idx >> 5;
            int c4  = idx & 31;
            float4 v = *(const float4*)(W + (size_t)(k0 + kr) * HID + c4 * 4);
            *(float4*)&Ws[kr][c4 * 4] = v;
        }
        __syncthreads();

#pragma unroll
        for (int k = 0; k < 32; k++) {
            float4 x0 = *(const float4*)&Xs[k][ty * 8];
            float4 x1 = *(const float4*)&Xs[k][ty * 8 + 4];
            float4 w0 = *(const float4*)&Ws[k][tx * 8];
            float4 w1 = *(const float4*)&Ws[k][tx * 8 + 4];
            float xr[8] = {x0.x, x0.y, x0.z, x0.w, x1.x, x1.y, x1.z, x1.w};
            float wr[8] = {w0.x, w0.y, w0.z, w0.w, w1.x, w1.y, w1.z, w1.w};
#pragma unroll
            for (int i = 0; i < 8; i++)
#pragma unroll
                for (int j = 0; j < 8; j++)
                    acc[i][j] = fmaf(xr[i], wr[j], acc[i][j]);
        }
        __syncthreads();
    }

#pragma unroll
    for (int i = 0; i < 8; i++) {
        int r = rowBase + ty * 8 + i;
        if (r >= M) break;
        size_t base = (size_t)r * HID + tx * 8;
        *(float4*)(H + base)     = make_float4(acc[i][0], acc[i][1], acc[i][2], acc[i][3]);
        *(float4*)(H + base + 4) = make_float4(acc[i][4], acc[i][5], acc[i][6], acc[i][7]);
    }
}

// ---------------- gather aggregation + bias + leaky ----------------
__global__ __launch_bounds__(256) void gather_kernel(
    const float* __restrict__ H, float* __restrict__ OUT,
    const int* __restrict__ rowptr, const int* __restrict__ csr_src,
    const float* __restrict__ csr_coef, const float* __restrict__ dinv,
    const float* __restrict__ bias)
{
    int n = blockIdx.x * 8 + (threadIdx.x >> 5);
    int lane = threadIdx.x & 31;
    if (n >= N_NODES) return;

    float di = __ldg(dinv + n);
    float sl = di * di;
    float4 a = *(const float4*)(H + (size_t)n * HID + lane * 4);
    float4 acc = make_float4(a.x * sl, a.y * sl, a.z * sl, a.w * sl);

    int i   = __ldg(rowptr + n);
    int end = __ldg(rowptr + n + 1);

    for (; i + 4 <= end; i += 4) {
        int s0 = __ldg(csr_src + i + 0);
        int s1 = __ldg(csr_src + i + 1);
        int s2 = __ldg(csr_src + i + 2);
        int s3 = __ldg(csr_src + i + 3);
        float c0 = __ldg(csr_coef + i + 0);
        float c1 = __ldg(csr_coef + i + 1);
        float c2 = __ldg(csr_coef + i + 2);
        float c3 = __ldg(csr_coef + i + 3);
        float4 v0 = *(const float4*)(H + (size_t)s0 * HID + lane * 4);
        float4 v1 = *(const float4*)(H + (size_t)s1 * HID + lane * 4);
        float4 v2 = *(const float4*)(H + (size_t)s2 * HID + lane * 4);
        float4 v3 = *(const float4*)(H + (size_t)s3 * HID + lane * 4);
        acc.x = fmaf(c0, v0.x, acc.x); acc.y = fmaf(c0, v0.y, acc.y);
        acc.z = fmaf(c0, v0.z, acc.z); acc.w = fmaf(c0, v0.w, acc.w);
        acc.x = fmaf(c1, v1.x, acc.x); acc.y = fmaf(c1, v1.y, acc.y);
        acc.z = fmaf(c1, v1.z, acc.z); acc.w = fmaf(c1, v1.w, acc.w);
        acc.x = fmaf(c2, v2.x, acc.x); acc.y = fmaf(c2, v2.y, acc.y);
        acc.z = fmaf(c2, v2.z, acc.z); acc.w = fmaf(c2, v2.w, acc.w);
        acc.x = fmaf(c3, v3.x, acc.x); acc.y = fmaf(c3, v3.y, acc.y);
        acc.z = fmaf(c3, v3.z, acc.z); acc.w = fmaf(c3, v3.w, acc.w);
    }
    for (; i < end; i++) {
        int s = __ldg(csr_src + i);
        float c = __ldg(csr_coef + i);
        float4 v = *(const float4*)(H + (size_t)s * HID + lane * 4);
        acc.x = fmaf(c, v.x, acc.x); acc.y = fmaf(c, v.y, acc.y);
        acc.z = fmaf(c, v.z, acc.z); acc.w = fmaf(c, v.w, acc.w);
    }

    float4 b = *(const float4*)(bias + lane * 4);
    acc.x = leaky(acc.x + b.x);
    acc.y = leaky(acc.y + b.y);
    acc.z = leaky(acc.z + b.z);
    acc.w = leaky(acc.w + b.w);
    *(float4*)(OUT + (size_t)n * HID + lane * 4) = acc;
}

// ---------------- pool ----------------
__global__ __launch_bounds__(256) void pool_kernel(
    const float* __restrict__ IN, const int* __restrict__ batch,
    float* __restrict__ pool, float* __restrict__ cnt)
{
    int t = blockIdx.x * blockDim.x + threadIdx.x;
    int n = t >> 5;
    int lane = t & 31;
    if (n >= N_NODES) return;
    int g = __ldg(batch + n);
    float4 v = *(const float4*)(IN + (size_t)n * HID + lane * 4);
    red_add_v4(pool + (size_t)g * HID + lane * 4, v.x, v.y, v.z, v.w);
    if (lane == 0) atomicAdd(&cnt[g], 1.0f);
}

// ---------------- finalize ----------------
__global__ void finalize_kernel(const float* __restrict__ pool, const float* __restrict__ cnt,
                                float* __restrict__ out)
{
    int i = blockIdx.x * blockDim.x + threadIdx.x;
    if (i >= N_GRAPHS * HID) return;
    int g = i >> 7;
    out[i] = pool[i] / fmaxf(cnt[g], 1.0f);
}

// ---------------- launch ----------------
extern "C" void kernel_launch(void* const* d_in, const int* in_sizes, int n_in,
                              void* d_out, int out_size)
{
    const float* drug_x = (const float*)d_in[0];
    const float* W1     = (const float*)d_in[1];
    const float* b1     = (const float*)d_in[2];
    const float* W2     = (const float*)d_in[3];
    const float* b2     = (const float*)d_in[4];
    const int*   eidx   = (const int*)d_in[5];
    const int*   batch  = (const int*)d_in[6];
    float* out = (float*)d_out;

    const int* src = eidx;
    const int* dst = eidx + N_EDGES;

    float *bufA, *bufB, *bufC, *dinv, *pool, *cnt, *csr_coef;
    int *count, *rowptr, *cursor, *csr_src, *blocksum, *blockoff;
    cudaGetSymbolAddress((void**)&bufA, g_bufA);
    cudaGetSymbolAddress((void**)&bufB, g_bufB);
    cudaGetSymbolAddress((void**)&bufC, g_bufC);
    cudaGetSymbolAddress((void**)&dinv, g_dinv);
    cudaGetSymbolAddress((void**)&pool, g_pool);
    cudaGetSymbolAddress((void**)&cnt,  g_cnt);
    cudaGetSymbolAddress((void**)&count,  g_count);
    cudaGetSymbolAddress((void**)&rowptr, g_rowptr);
    cudaGetSymbolAddress((void**)&cursor, g_cursor);
    cudaGetSymbolAddress((void**)&csr_src,  g_csr_src);
    cudaGetSymbolAddress((void**)&csr_coef, g_csr_coef);
    cudaGetSymbolAddress((void**)&blocksum, g_blocksum);
    cudaGetSymbolAddress((void**)&blockoff, g_blockoff);

    const int T = 256;
    int gemm_blocks = (N_NODES + 127) / 128;
    int gath_blocks = (N_NODES + 7) / 8;
    int poolb       = (N_NODES * 32 + T - 1) / T;

    // CSR build
    init_kernel<<<(N_GRAPHS * HID + T - 1) / T, T>>>(pool, cnt, count);
    hist_kernel<<<(N_EDGES + T - 1) / T, T>>>(dst, count);
    dinv_kernel<<<(N_NODES + T - 1) / T, T>>>(count, dinv);
    blocksum_kernel<<<SCAN_B, SCAN_T>>>(count, blocksum);
    scanblock_kernel<<<1, 256>>>(blocksum, blockoff);
    writeptr_kernel<<<SCAN_B, SCAN_T>>>(count, blockoff, rowptr, cursor);
    fill_kernel<<<(N_EDGES + T - 1) / T, T>>>(src, dst, dinv, cursor, csr_src, csr_coef);

    // layer 1
    gemm_kernel<<<gemm_blocks, T>>>(drug_x, W1, bufA, N_NODES);
    gather_kernel<<<gath_blocks, T>>>(bufA, bufC, rowptr, csr_src, csr_coef, dinv, b1);

    // layer 2
    gemm_kernel<<<gemm_blocks, T>>>(bufC, W2, bufA, N_NODES);
    gather_kernel<<<gath_blocks, T>>>(bufA, bufB, rowptr, csr_src, csr_coef, dinv, b2);

    // mean pool
    pool_kernel<<<poolb, T>>>(bufB, batch, pool, cnt);
    finalize_kernel<<<(N_GRAPHS * HID + T - 1) / T, T>>>(pool, cnt, out);
}

// round 6
// speedup vs baseline: 1.7092x; 1.1710x over previous
#include <cuda_runtime.h>
#include <cuda_bf16.h>
#include <cstdint>

#define N_NODES 50000
#define N_EDGES 600000
#define N_GRAPHS 1000
#define HID 128
#define NEG_SLOPE 0.01f

#define SCAN_T 256
#define SCAN_B ((N_NODES + SCAN_T - 1) / SCAN_T)   // 196

// ---------------- scratch (static device globals; no allocation) ----------------
__device__ float g_bufA[(size_t)N_NODES * HID];
__device__ float g_bufB[(size_t)N_NODES * HID];
__device__ float g_bufC[(size_t)N_NODES * HID];
__device__ float g_dinv[N_NODES];
__device__ float g_pool[N_GRAPHS * HID];
__device__ float g_cnt[N_GRAPHS];
__device__ int   g_count[N_NODES];
__device__ int   g_rowptr[N_NODES + 1];
__device__ int   g_cursor[N_NODES];
__device__ int   g_csr_src[N_EDGES];
__device__ float g_csr_coef[N_EDGES];
__device__ int   g_blocksum[SCAN_B];
__device__ int   g_blockoff[SCAN_B];
// W^T bf16 hi/lo images [N=128][K=128] row-major
__device__ __nv_bfloat16 g_wt1_hi[HID * HID];
__device__ __nv_bfloat16 g_wt1_lo[HID * HID];
__device__ __nv_bfloat16 g_wt2_hi[HID * HID];
__device__ __nv_bfloat16 g_wt2_lo[HID * HID];

// ---------------- helpers ----------------
__device__ __forceinline__ float leaky(float x) {
    return x > 0.0f ? x : NEG_SLOPE * x;
}

__device__ __forceinline__ void red_add_v4(float* addr, float a, float b, float c, float d) {
    asm volatile("red.global.add.v4.f32 [%0], {%1, %2, %3, %4};"
                 :: "l"(addr), "f"(a), "f"(b), "f"(c), "f"(d) : "memory");
}

// portable bf16 warp MMA: D(16x8,f32) += A(16x16,bf16) * B(16x8,bf16)
__device__ __forceinline__ void mma_bf16(float* d,
                                         uint32_t a0, uint32_t a1, uint32_t a2, uint32_t a3,
                                         uint32_t b0, uint32_t b1) {
    asm volatile("mma.sync.aligned.m16n8k16.row.col.f32.bf16.bf16.f32 "
                 "{%0,%1,%2,%3}, {%4,%5,%6,%7}, {%8,%9}, {%0,%1,%2,%3};"
                 : "+f"(d[0]), "+f"(d[1]), "+f"(d[2]), "+f"(d[3])
                 : "r"(a0), "r"(a1), "r"(a2), "r"(a3), "r"(b0), "r"(b1));
}

// ---------------- init: zero pool/cnt/count ----------------
__global__ void init_kernel(float* pool, float* cnt, int* count) {
    int i = blockIdx.x * blockDim.x + threadIdx.x;
    if (i < N_GRAPHS * HID) pool[i] = 0.0f;
    if (i < N_NODES) count[i] = 0;
    if (i < N_GRAPHS) cnt[i] = 0.0f;
}

// ---------------- degree histogram over dst ----------------
__global__ void hist_kernel(const int* __restrict__ dst, int* __restrict__ count) {
    int e = blockIdx.x * blockDim.x + threadIdx.x;
    if (e < N_EDGES) atomicAdd(&count[dst[e]], 1);
}

__global__ void dinv_kernel(const int* __restrict__ count, float* __restrict__ dinv) {
    int i = blockIdx.x * blockDim.x + threadIdx.x;
    if (i < N_NODES) dinv[i] = rsqrtf((float)count[i] + 1.0f);
}

// ---------------- grid-wide scan (3 phases) ----------------
__global__ __launch_bounds__(SCAN_T) void blocksum_kernel(const int* __restrict__ count,
                                                          int* __restrict__ blocksum)
{
    __shared__ int warpsum[SCAN_T / 32];
    int i = blockIdx.x * SCAN_T + threadIdx.x;
    int v = (i < N_NODES) ? count[i] : 0;
#pragma unroll
    for (int off = 16; off > 0; off >>= 1)
        v += __shfl_down_sync(0xffffffffu, v, off);
    if ((threadIdx.x & 31) == 0) warpsum[threadIdx.x >> 5] = v;
    __syncthreads();
    if (threadIdx.x < SCAN_T / 32) {
        int s = warpsum[threadIdx.x];
#pragma unroll
        for (int off = SCAN_T / 64; off > 0; off >>= 1)
            s += __shfl_down_sync(0xffu, s, off);
        if (threadIdx.x == 0) blocksum[blockIdx.x] = s;
    }
}

__global__ __launch_bounds__(256) void scanblock_kernel(const int* __restrict__ blocksum,
                                                        int* __restrict__ blockoff)
{
    __shared__ int warptot[8];
    int t = threadIdx.x;
    int v = (t < SCAN_B) ? blocksum[t] : 0;
    int lane = t & 31, w = t >> 5;
    int x = v;
#pragma unroll
    for (int off = 1; off < 32; off <<= 1) {
        int y = __shfl_up_sync(0xffffffffu, x, off);
        if (lane >= off) x += y;
    }
    if (lane == 31) warptot[w] = x;
    __syncthreads();
    if (t < 8) {
        int s = warptot[t];
#pragma unroll
        for (int off = 1; off < 8; off <<= 1) {
            int y = __shfl_up_sync(0xffu, s, off);
            if (t >= off) s += y;
        }
        warptot[t] = s;
    }
    __syncthreads();
    int excl = x - v + (w > 0 ? warptot[w - 1] : 0);
    if (t < SCAN_B) blockoff[t] = excl;
}

__global__ __launch_bounds__(SCAN_T) void writeptr_kernel(const int* __restrict__ count,
                                                          const int* __restrict__ blockoff,
                                                          int* __restrict__ rowptr,
                                                          int* __restrict__ cursor)
{
    __shared__ int warptot[SCAN_T / 32];
    int i = blockIdx.x * SCAN_T + threadIdx.x;
    int v = (i < N_NODES) ? count[i] : 0;
    int lane = threadIdx.x & 31, w = threadIdx.x >> 5;
    int x = v;
#pragma unroll
    for (int off = 1; off < 32; off <<= 1) {
        int y = __shfl_up_sync(0xffffffffu, x, off);
        if (lane >= off) x += y;
    }
    if (lane == 31) warptot[w] = x;
    __syncthreads();
    if (threadIdx.x < SCAN_T / 32) {
        int s = warptot[threadIdx.x];
#pragma unroll
        for (int off = 1; off < SCAN_T / 32; off <<= 1) {
            int y = __shfl_up_sync(0xffu, s, off);
            if ((int)threadIdx.x >= off) s += y;
        }
        warptot[threadIdx.x] = s;
    }
    __syncthreads();
    int excl = x - v + (w > 0 ? warptot[w - 1] : 0) + blockoff[blockIdx.x];
    if (i < N_NODES) {
        rowptr[i] = excl;
        cursor[i] = excl;
    }
    if (i == 0) rowptr[N_NODES] = N_EDGES;
}

// ---------------- fill CSR ----------------
__global__ void fill_kernel(const int* __restrict__ src, const int* __restrict__ dst,
                            const float* __restrict__ dinv, int* __restrict__ cursor,
                            int* __restrict__ csr_src, float* __restrict__ csr_coef)
{
    int e = blockIdx.x * blockDim.x + threadIdx.x;
    if (e >= N_EDGES) return;
    int s = __ldg(src + e);
    int d = __ldg(dst + e);
    int p = atomicAdd(&cursor[d], 1);
    csr_src[p] = s;
    csr_coef[p] = __ldg(dinv + s) * __ldg(dinv + d);
}

// ---------------- W prep: W[k][n] fp32 -> W^T[n][k] bf16 hi/lo ----------------
__global__ void wprep_kernel(const float* __restrict__ W,
                             __nv_bfloat16* __restrict__ wt_hi,
                             __nv_bfloat16* __restrict__ wt_lo)
{
    int i = blockIdx.x * blockDim.x + threadIdx.x;  // i = k*128 + n (coalesced read)
    if (i >= HID * HID) return;
    int n = i & 127, k = i >> 7;
    float v = W[i];
    __nv_bfloat16 h = __float2bfloat16(v);
    __nv_bfloat16 l = __float2bfloat16(v - __bfloat162float(h));
    wt_hi[n * HID + k] = h;
    wt_lo[n * HID + k] = l;
}

// ---------------- warp-MMA GEMM: H = X*W (split-bf16, fp32 accum) ----------------
// 128x128 CTA tile, 8 warps (4 M x 2 N), warp tile 32x64, K=128 in one shot.
#define AS 132                       // padded row stride (bf16 elements) = 264 B
#define SM_AH 0
#define SM_AL (SM_AH + 128 * AS * 2)
#define SM_BH (SM_AL + 128 * AS * 2)
#define SM_BL (SM_BH + 128 * AS * 2)
#define SM_GEMM_TOTAL (SM_BL + 128 * AS * 2)   // 135168 B

__global__ __launch_bounds__(256) void gemm_mma_kernel(
    const float* __restrict__ X,
    const __nv_bfloat16* __restrict__ wt_hi,
    const __nv_bfloat16* __restrict__ wt_lo,
    float* __restrict__ H, int M)
{
    extern __shared__ char smem[];
    const int tid = threadIdx.x;
    const int wid = tid >> 5;
    const int lane = tid & 31;
    const int rowBase = blockIdx.x * 128;

    // --- load A: fp32 -> split bf16 hi/lo; 2 threads per row, 64 k each ---
    {
        int row = tid >> 1;
        int half = tid & 1;
        int gr = rowBase + row;
        const float4* xr = (const float4*)(X + (size_t)gr * HID + half * 64);
        char* ah = smem + SM_AH + row * (AS * 2) + half * 128;
        char* al = smem + SM_AL + row * (AS * 2) + half * 128;
#pragma unroll
        for (int k4 = 0; k4 < 16; k4++) {
            float4 v = (gr < M) ? __ldg(&xr[k4]) : make_float4(0.f, 0.f, 0.f, 0.f);
            __nv_bfloat16 h0 = __float2bfloat16(v.x), h1 = __float2bfloat16(v.y);
            __nv_bfloat16 h2 = __float2bfloat16(v.z), h3 = __float2bfloat16(v.w);
            __nv_bfloat16 l0 = __float2bfloat16(v.x - __bfloat162float(h0));
            __nv_bfloat16 l1 = __float2bfloat16(v.y - __bfloat162float(h1));
            __nv_bfloat16 l2 = __float2bfloat16(v.z - __bfloat162float(h2));
            __nv_bfloat16 l3 = __float2bfloat16(v.w - __bfloat162float(h3));
            uint2 hp, lp;
            hp.x = (uint32_t)__bfloat16_as_ushort(h0) | ((uint32_t)__bfloat16_as_ushort(h1) << 16);
            hp.y = (uint32_t)__bfloat16_as_ushort(h2) | ((uint32_t)__bfloat16_as_ushort(h3) << 16);
            lp.x = (uint32_t)__bfloat16_as_ushort(l0) | ((uint32_t)__bfloat16_as_ushort(l1) << 16);
            lp.y = (uint32_t)__bfloat16_as_ushort(l2) | ((uint32_t)__bfloat16_as_ushort(l3) << 16);
            *(uint2*)(ah + k4 * 8) = hp;
            *(uint2*)(al + k4 * 8) = lp;
        }
    }
    // --- load B: copy W^T hi/lo into padded smem (32-bit words) ---
    {
        const uint32_t* gh = (const uint32_t*)wt_hi;
        const uint32_t* gl = (const uint32_t*)wt_lo;
#pragma unroll
        for (int w = 0; w < 32; w++) {
            int wi = tid + w * 256;            // word index 0..8191
            int r = wi >> 6, c = wi & 63;      // row, word-col
            *(uint32_t*)(smem + SM_BH + r * (AS * 2) + c * 4) = __ldg(&gh[r * 64 + c]);
            *(uint32_t*)(smem + SM_BL + r * (AS * 2) + c * 4) = __ldg(&gl[r * 64 + c]);
        }
    }
    __syncthreads();

    const int g = lane >> 2, t = lane & 3;
    const int mOff = (wid & 3) * 32;
    const int nOff = (wid >> 2) * 64;

    float acc[2][8][4];
#pragma unroll
    for (int i = 0; i < 2; i++)
#pragma unroll
        for (int j = 0; j < 8; j++)
#pragma unroll
            for (int q = 0; q < 4; q++) acc[i][j][q] = 0.0f;

#pragma unroll
    for (int ks = 0; ks < 8; ks++) {
        int k0 = ks * 16;
        uint32_t ah[2][4], al[2][4];
#pragma unroll
        for (int i = 0; i < 2; i++) {
            int r0 = mOff + i * 16 + g;
            const char* pah = smem + SM_AH;
            const char* pal = smem + SM_AL;
            ah[i][0] = *(const uint32_t*)(pah + (r0)     * (AS * 2) + (k0 + t * 2) * 2);
            ah[i][1] = *(const uint32_t*)(pah + (r0 + 8) * (AS * 2) + (k0 + t * 2) * 2);
            ah[i][2] = *(const uint32_t*)(pah + (r0)     * (AS * 2) + (k0 + t * 2 + 8) * 2);
            ah[i][3] = *(const uint32_t*)(pah + (r0 + 8) * (AS * 2) + (k0 + t * 2 + 8) * 2);
            al[i][0] = *(const uint32_t*)(pal + (r0)     * (AS * 2) + (k0 + t * 2) * 2);
            al[i][1] = *(const uint32_t*)(pal + (r0 + 8) * (AS * 2) + (k0 + t * 2) * 2);
            al[i][2] = *(const uint32_t*)(pal + (r0)     * (AS * 2) + (k0 + t * 2 + 8) * 2);
            al[i][3] = *(const uint32_t*)(pal + (r0 + 8) * (AS * 2) + (k0 + t * 2 + 8) * 2);
        }
#pragma unroll
        for (int j = 0; j < 8; j++) {
            int n0 = nOff + j * 8 + g;
            uint32_t bh0 = *(const uint32_t*)(smem + SM_BH + n0 * (AS * 2) + (k0 + t * 2) * 2);
            uint32_t bh1 = *(const uint32_t*)(smem + SM_BH + n0 * (AS * 2) + (k0 + t * 2 + 8) * 2);
            uint32_t bl0 = *(const uint32_t*)(smem + SM_BL + n0 * (AS * 2) + (k0 + t * 2) * 2);
            uint32_t bl1 = *(const uint32_t*)(smem + SM_BL + n0 * (AS * 2) + (k0 + t * 2 + 8) * 2);
#pragma unroll
            for (int i = 0; i < 2; i++) {
                mma_bf16(acc[i][j], ah[i][0], ah[i][1], ah[i][2], ah[i][3], bh0, bh1);
                mma_bf16(acc[i][j], ah[i][0], ah[i][1], ah[i][2], ah[i][3], bl0, bl1);
                mma_bf16(acc[i][j], al[i][0], al[i][1], al[i][2], al[i][3], bh0, bh1);
            }
        }
    }

    // --- epilogue ---
#pragma unroll
    for (int i = 0; i < 2; i++) {
#pragma unroll
        for (int j = 0; j < 8; j++) {
            int row = rowBase + mOff + i * 16 + g;
            int col = nOff + j * 8 + t * 2;
            if (row < M)
                *(float2*)(H + (size_t)row * HID + col) = make_float2(acc[i][j][0], acc[i][j][1]);
            if (row + 8 < M)
                *(float2*)(H + (size_t)(row + 8) * HID + col) = make_float2(acc[i][j][2], acc[i][j][3]);
        }
    }
}

// ---------------- gather aggregation + bias + leaky ----------------
__global__ __launch_bounds__(256) void gather_kernel(
    const float* __restrict__ H, float* __restrict__ OUT,
    const int* __restrict__ rowptr, const int* __restrict__ csr_src,
    const float* __restrict__ csr_coef, const float* __restrict__ dinv,
    const float* __restrict__ bias)
{
    int n = blockIdx.x * 8 + (threadIdx.x >> 5);
    int lane = threadIdx.x & 31;
    if (n >= N_NODES) return;

    float di = __ldg(dinv + n);
    float sl = di * di;
    float4 a = *(const float4*)(H + (size_t)n * HID + lane * 4);
    float4 acc = make_float4(a.x * sl, a.y * sl, a.z * sl, a.w * sl);

    int i   = __ldg(rowptr + n);
    int end = __ldg(rowptr + n + 1);

    for (; i + 4 <= end; i += 4) {
        int s0 = __ldg(csr_src + i + 0);
        int s1 = __ldg(csr_src + i + 1);
        int s2 = __ldg(csr_src + i + 2);
        int s3 = __ldg(csr_src + i + 3);
        float c0 = __ldg(csr_coef + i + 0);
        float c1 = __ldg(csr_coef + i + 1);
        float c2 = __ldg(csr_coef + i + 2);
        float c3 = __ldg(csr_coef + i + 3);
        float4 v0 = *(const float4*)(H + (size_t)s0 * HID + lane * 4);
        float4 v1 = *(const float4*)(H + (size_t)s1 * HID + lane * 4);
        float4 v2 = *(const float4*)(H + (size_t)s2 * HID + lane * 4);
        float4 v3 = *(const float4*)(H + (size_t)s3 * HID + lane * 4);
        acc.x = fmaf(c0, v0.x, acc.x); acc.y = fmaf(c0, v0.y, acc.y);
        acc.z = fmaf(c0, v0.z, acc.z); acc.w = fmaf(c0, v0.w, acc.w);
        acc.x = fmaf(c1, v1.x, acc.x); acc.y = fmaf(c1, v1.y, acc.y);
        acc.z = fmaf(c1, v1.z, acc.z); acc.w = fmaf(c1, v1.w, acc.w);
        acc.x = fmaf(c2, v2.x, acc.x); acc.y = fmaf(c2, v2.y, acc.y);
        acc.z = fmaf(c2, v2.z, acc.z); acc.w = fmaf(c2, v2.w, acc.w);
        acc.x = fmaf(c3, v3.x, acc.x); acc.y = fmaf(c3, v3.y, acc.y);
        acc.z = fmaf(c3, v3.z, acc.z); acc.w = fmaf(c3, v3.w, acc.w);
    }
    for (; i < end; i++) {
        int s = __ldg(csr_src + i);
        float c = __ldg(csr_coef + i);
        float4 v = *(const float4*)(H + (size_t)s * HID + lane * 4);
        acc.x = fmaf(c, v.x, acc.x); acc.y = fmaf(c, v.y, acc.y);
        acc.z = fmaf(c, v.z, acc.z); acc.w = fmaf(c, v.w, acc.w);
    }

    float4 b = *(const float4*)(bias + lane * 4);
    acc.x = leaky(acc.x + b.x);
    acc.y = leaky(acc.y + b.y);
    acc.z = leaky(acc.z + b.z);
    acc.w = leaky(acc.w + b.w);
    *(float4*)(OUT + (size_t)n * HID + lane * 4) = acc;
}

// ---------------- pool ----------------
__global__ __launch_bounds__(256) void pool_kernel(
    const float* __restrict__ IN, const int* __restrict__ batch,
    float* __restrict__ pool, float* __restrict__ cnt)
{
    int t = blockIdx.x * blockDim.x + threadIdx.x;
    int n = t >> 5;
    int lane = t & 31;
    if (n >= N_NODES) return;
    int g = __ldg(batch + n);
    float4 v = *(const float4*)(IN + (size_t)n * HID + lane * 4);
    red_add_v4(pool + (size_t)g * HID + lane * 4, v.x, v.y, v.z, v.w);
    if (lane == 0) atomicAdd(&cnt[g], 1.0f);
}

// ---------------- finalize ----------------
__global__ void finalize_kernel(const float* __restrict__ pool, const float* __restrict__ cnt,
                                float* __restrict__ out)
{
    int i = blockIdx.x * blockDim.x + threadIdx.x;
    if (i >= N_GRAPHS * HID) return;
    int g = i >> 7;
    out[i] = pool[i] / fmaxf(cnt[g], 1.0f);
}

// ---------------- launch ----------------
extern "C" void kernel_launch(void* const* d_in, const int* in_sizes, int n_in,
                              void* d_out, int out_size)
{
    const float* drug_x = (const float*)d_in[0];
    const float* W1     = (const float*)d_in[1];
    const float* b1     = (const float*)d_in[2];
    const float* W2     = (const float*)d_in[3];
    const float* b2     = (const float*)d_in[4];
    const int*   eidx   = (const int*)d_in[5];
    const int*   batch  = (const int*)d_in[6];
    float* out = (float*)d_out;

    const int* src = eidx;
    const int* dst = eidx + N_EDGES;

    float *bufA, *bufB, *bufC, *dinv, *pool, *cnt, *csr_coef;
    int *count, *rowptr, *cursor, *csr_src, *blocksum, *blockoff;
    __nv_bfloat16 *w1h, *w1l, *w2h, *w2l;
    cudaGetSymbolAddress((void**)&bufA, g_bufA);
    cudaGetSymbolAddress((void**)&bufB, g_bufB);
    cudaGetSymbolAddress((void**)&bufC, g_bufC);
    cudaGetSymbolAddress((void**)&dinv, g_dinv);
    cudaGetSymbolAddress((void**)&pool, g_pool);
    cudaGetSymbolAddress((void**)&cnt,  g_cnt);
    cudaGetSymbolAddress((void**)&count,  g_count);
    cudaGetSymbolAddress((void**)&rowptr, g_rowptr);
    cudaGetSymbolAddress((void**)&cursor, g_cursor);
    cudaGetSymbolAddress((void**)&csr_src,  g_csr_src);
    cudaGetSymbolAddress((void**)&csr_coef, g_csr_coef);
    cudaGetSymbolAddress((void**)&blocksum, g_blocksum);
    cudaGetSymbolAddress((void**)&blockoff, g_blockoff);
    cudaGetSymbolAddress((void**)&w1h, g_wt1_hi);
    cudaGetSymbolAddress((void**)&w1l, g_wt1_lo);
    cudaGetSymbolAddress((void**)&w2h, g_wt2_hi);
    cudaGetSymbolAddress((void**)&w2l, g_wt2_lo);

    cudaFuncSetAttribute(gemm_mma_kernel, cudaFuncAttributeMaxDynamicSharedMemorySize,
                         SM_GEMM_TOTAL);

    const int T = 256;
    int gemm_blocks = (N_NODES + 127) / 128;   // 391
    int gath_blocks = (N_NODES + 7) / 8;
    int poolb       = (N_NODES * 32 + T - 1) / T;

    // CSR build + W prep
    init_kernel<<<(N_GRAPHS * HID + T - 1) / T, T>>>(pool, cnt, count);
    wprep_kernel<<<(HID * HID + T - 1) / T, T>>>(W1, w1h, w1l);
    wprep_kernel<<<(HID * HID + T - 1) / T, T>>>(W2, w2h, w2l);
    hist_kernel<<<(N_EDGES + T - 1) / T, T>>>(dst, count);
    dinv_kernel<<<(N_NODES + T - 1) / T, T>>>(count, dinv);
    blocksum_kernel<<<SCAN_B, SCAN_T>>>(count, blocksum);
    scanblock_kernel<<<1, 256>>>(blocksum, blockoff);
    writeptr_kernel<<<SCAN_B, SCAN_T>>>(count, blockoff, rowptr, cursor);
    fill_kernel<<<(N_EDGES + T - 1) / T, T>>>(src, dst, dinv, cursor, csr_src, csr_coef);

    // layer 1
    gemm_mma_kernel<<<gemm_blocks, T, SM_GEMM_TOTAL>>>(drug_x, w1h, w1l, bufA, N_NODES);
    gather_kernel<<<gath_blocks, T>>>(bufA, bufC, rowptr, csr_src, csr_coef, dinv, b1);

    // layer 2
    gemm_mma_kernel<<<gemm_blocks, T, SM_GEMM_TOTAL>>>(bufC, w2h, w2l, bufA, N_NODES);
    gather_kernel<<<gath_blocks, T>>>(bufA, bufB, rowptr, csr_src, csr_coef, dinv, b2);

    // mean pool
    pool_kernel<<<poolb, T>>>(bufB, batch, pool, cnt);
    finalize_kernel<<<(N_GRAPHS * HID + T - 1) / T, T>>>(pool, cnt, out);
}

// round 7
// speedup vs baseline: 1.8813x; 1.1007x over previous
#include <cuda_runtime.h>
#include <cuda_bf16.h>
#include <cstdint>

#define N_NODES 50000
#define N_EDGES 600000
#define N_GRAPHS 1000
#define HID 128
#define NEG_SLOPE 0.01f

#define SCAN_T 256
#define SCAN_B ((N_NODES + SCAN_T - 1) / SCAN_T)   // 196

// ---------------- scratch (static device globals; no allocation) ----------------
__device__ float g_bufA[(size_t)N_NODES * HID];
__device__ float g_bufC[(size_t)N_NODES * HID];
__device__ float g_dinv[N_NODES];
__device__ float g_pool[N_GRAPHS * HID];
__device__ float g_cnt[N_GRAPHS];
__device__ int   g_count[N_NODES];
__device__ int   g_rowptr[N_NODES + 1];
__device__ int   g_cursor[N_NODES];
__device__ int2  g_csr[N_EDGES];          // {src, coef-as-int}
__device__ int   g_blocksum[SCAN_B];
__device__ int   g_blockoff[SCAN_B];
// W^T bf16 hi/lo images [N=128][K=128] row-major
__device__ __nv_bfloat16 g_wt1_hi[HID * HID];
__device__ __nv_bfloat16 g_wt1_lo[HID * HID];
__device__ __nv_bfloat16 g_wt2_hi[HID * HID];
__device__ __nv_bfloat16 g_wt2_lo[HID * HID];

// ---------------- helpers ----------------
__device__ __forceinline__ float leaky(float x) {
    return x > 0.0f ? x : NEG_SLOPE * x;
}

__device__ __forceinline__ void red_add_v4(float* addr, float a, float b, float c, float d) {
    asm volatile("red.global.add.v4.f32 [%0], {%1, %2, %3, %4};"
                 :: "l"(addr), "f"(a), "f"(b), "f"(c), "f"(d) : "memory");
}

// portable bf16 warp MMA: D(16x8,f32) += A(16x16,bf16) * B(16x8,bf16)
__device__ __forceinline__ void mma_bf16(float* d,
                                         uint32_t a0, uint32_t a1, uint32_t a2, uint32_t a3,
                                         uint32_t b0, uint32_t b1) {
    asm volatile("mma.sync.aligned.m16n8k16.row.col.f32.bf16.bf16.f32 "
                 "{%0,%1,%2,%3}, {%4,%5,%6,%7}, {%8,%9}, {%0,%1,%2,%3};"
                 : "+f"(d[0]), "+f"(d[1]), "+f"(d[2]), "+f"(d[3])
                 : "r"(a0), "r"(a1), "r"(a2), "r"(a3), "r"(b0), "r"(b1));
}

// ---------------- init: zero pool/cnt/count ----------------
__global__ void init_kernel(float* pool, float* cnt, int* count) {
    int i = blockIdx.x * blockDim.x + threadIdx.x;
    if (i < N_GRAPHS * HID) pool[i] = 0.0f;
    if (i < N_NODES) count[i] = 0;
    if (i < N_GRAPHS) cnt[i] = 0.0f;
}

// ---------------- degree histogram over dst (int4, 4 edges/thread) ----------------
__global__ void hist_kernel(const int* __restrict__ dst, int* __restrict__ count) {
    int t = blockIdx.x * blockDim.x + threadIdx.x;
    if (t >= N_EDGES / 4) return;
    int4 d = __ldg((const int4*)dst + t);
    atomicAdd(&count[d.x], 1);
    atomicAdd(&count[d.y], 1);
    atomicAdd(&count[d.z], 1);
    atomicAdd(&count[d.w], 1);
}

// ---------------- scan phase 1 + dinv (same pass over count) ----------------
__global__ __launch_bounds__(SCAN_T) void blocksum_dinv_kernel(const int* __restrict__ count,
                                                               int* __restrict__ blocksum,
                                                               float* __restrict__ dinv)
{
    __shared__ int warpsum[SCAN_T / 32];
    int i = blockIdx.x * SCAN_T + threadIdx.x;
    int v = (i < N_NODES) ? count[i] : 0;
    if (i < N_NODES) dinv[i] = rsqrtf((float)v + 1.0f);
    int s = v;
#pragma unroll
    for (int off = 16; off > 0; off >>= 1)
        s += __shfl_down_sync(0xffffffffu, s, off);
    if ((threadIdx.x & 31) == 0) warpsum[threadIdx.x >> 5] = s;
    __syncthreads();
    if (threadIdx.x < SCAN_T / 32) {
        int w = warpsum[threadIdx.x];
#pragma unroll
        for (int off = SCAN_T / 64; off > 0; off >>= 1)
            w += __shfl_down_sync(0xffu, w, off);
        if (threadIdx.x == 0) blocksum[blockIdx.x] = w;
    }
}

__global__ __launch_bounds__(256) void scanblock_kernel(const int* __restrict__ blocksum,
                                                        int* __restrict__ blockoff)
{
    __shared__ int warptot[8];
    int t = threadIdx.x;
    int v = (t < SCAN_B) ? blocksum[t] : 0;
    int lane = t & 31, w = t >> 5;
    int x = v;
#pragma unroll
    for (int off = 1; off < 32; off <<= 1) {
        int y = __shfl_up_sync(0xffffffffu, x, off);
        if (lane >= off) x += y;
    }
    if (lane == 31) warptot[w] = x;
    __syncthreads();
    if (t < 8) {
        int s = warptot[t];
#pragma unroll
        for (int off = 1; off < 8; off <<= 1) {
            int y = __shfl_up_sync(0xffu, s, off);
            if (t >= off) s += y;
        }
        warptot[t] = s;
    }
    __syncthreads();
    int excl = x - v + (w > 0 ? warptot[w - 1] : 0);
    if (t < SCAN_B) blockoff[t] = excl;
}

__global__ __launch_bounds__(SCAN_T) void writeptr_kernel(const int* __restrict__ count,
                                                          const int* __restrict__ blockoff,
                                                          int* __restrict__ rowptr,
                                                          int* __restrict__ cursor)
{
    __shared__ int warptot[SCAN_T / 32];
    int i = blockIdx.x * SCAN_T + threadIdx.x;
    int v = (i < N_NODES) ? count[i] : 0;
    int lane = threadIdx.x & 31, w = threadIdx.x >> 5;
    int x = v;
#pragma unroll
    for (int off = 1; off < 32; off <<= 1) {
        int y = __shfl_up_sync(0xffffffffu, x, off);
        if (lane >= off) x += y;
    }
    if (lane == 31) warptot[w] = x;
    __syncthreads();
    if (threadIdx.x < SCAN_T / 32) {
        int s = warptot[threadIdx.x];
#pragma unroll
        for (int off = 1; off < SCAN_T / 32; off <<= 1) {
            int y = __shfl_up_sync(0xffu, s, off);
            if ((int)threadIdx.x >= off) s += y;
        }
        warptot[threadIdx.x] = s;
    }
    __syncthreads();
    int excl = x - v + (w > 0 ? warptot[w - 1] : 0) + blockoff[blockIdx.x];
    if (i < N_NODES) {
        rowptr[i] = excl;
        cursor[i] = excl;
    }
    if (i == 0) rowptr[N_NODES] = N_EDGES;
}

// ---------------- fill CSR (packed int2) ----------------
__global__ void fill_kernel(const int* __restrict__ src, const int* __restrict__ dst,
                            const float* __restrict__ dinv, int* __restrict__ cursor,
                            int2* __restrict__ csr)
{
    int e = blockIdx.x * blockDim.x + threadIdx.x;
    if (e >= N_EDGES) return;
    int s = __ldg(src + e);
    int d = __ldg(dst + e);
    int p = atomicAdd(&cursor[d], 1);
    float coef = __ldg(dinv + s) * __ldg(dinv + d);
    csr[p] = make_int2(s, __float_as_int(coef));
}

// ---------------- W prep: W[k][n] fp32 -> W^T[n][k] bf16 hi/lo ----------------
__global__ void wprep_kernel(const float* __restrict__ W,
                             __nv_bfloat16* __restrict__ wt_hi,
                             __nv_bfloat16* __restrict__ wt_lo)
{
    int i = blockIdx.x * blockDim.x + threadIdx.x;
    if (i >= HID * HID) return;
    int n = i & 127, k = i >> 7;
    float v = W[i];
    __nv_bfloat16 h = __float2bfloat16(v);
    __nv_bfloat16 l = __float2bfloat16(v - __bfloat162float(h));
    wt_hi[n * HID + k] = h;
    wt_lo[n * HID + k] = l;
}

// ---------------- warp-MMA GEMM: H = X*W (split-bf16, fp32 accum) ----------------
#define AS 132
#define SM_AH 0
#define SM_AL (SM_AH + 128 * AS * 2)
#define SM_BH (SM_AL + 128 * AS * 2)
#define SM_BL (SM_BH + 128 * AS * 2)
#define SM_GEMM_TOTAL (SM_BL + 128 * AS * 2)   // 135168 B

__global__ __launch_bounds__(256) void gemm_mma_kernel(
    const float* __restrict__ X,
    const __nv_bfloat16* __restrict__ wt_hi,
    const __nv_bfloat16* __restrict__ wt_lo,
    float* __restrict__ H, int M)
{
    extern __shared__ char smem[];
    const int tid = threadIdx.x;
    const int wid = tid >> 5;
    const int lane = tid & 31;
    const int rowBase = blockIdx.x * 128;

    {
        int row = tid >> 1;
        int half = tid & 1;
        int gr = rowBase + row;
        const float4* xr = (const float4*)(X + (size_t)gr * HID + half * 64);
        char* ah = smem + SM_AH + row * (AS * 2) + half * 128;
        char* al = smem + SM_AL + row * (AS * 2) + half * 128;
#pragma unroll
        for (int k4 = 0; k4 < 16; k4++) {
            float4 v = (gr < M) ? __ldg(&xr[k4]) : make_float4(0.f, 0.f, 0.f, 0.f);
            __nv_bfloat16 h0 = __float2bfloat16(v.x), h1 = __float2bfloat16(v.y);
            __nv_bfloat16 h2 = __float2bfloat16(v.z), h3 = __float2bfloat16(v.w);
            __nv_bfloat16 l0 = __float2bfloat16(v.x - __bfloat162float(h0));
            __nv_bfloat16 l1 = __float2bfloat16(v.y - __bfloat162float(h1));
            __nv_bfloat16 l2 = __float2bfloat16(v.z - __bfloat162float(h2));
            __nv_bfloat16 l3 = __float2bfloat16(v.w - __bfloat162float(h3));
            uint2 hp, lp;
            hp.x = (uint32_t)__bfloat16_as_ushort(h0) | ((uint32_t)__bfloat16_as_ushort(h1) << 16);
            hp.y = (uint32_t)__bfloat16_as_ushort(h2) | ((uint32_t)__bfloat16_as_ushort(h3) << 16);
            lp.x = (uint32_t)__bfloat16_as_ushort(l0) | ((uint32_t)__bfloat16_as_ushort(l1) << 16);
            lp.y = (uint32_t)__bfloat16_as_ushort(l2) | ((uint32_t)__bfloat16_as_ushort(l3) << 16);
            *(uint2*)(ah + k4 * 8) = hp;
            *(uint2*)(al + k4 * 8) = lp;
        }
    }
    {
        const uint32_t* gh = (const uint32_t*)wt_hi;
        const uint32_t* gl = (const uint32_t*)wt_lo;
#pragma unroll
        for (int w = 0; w < 32; w++) {
            int wi = tid + w * 256;
            int r = wi >> 6, c = wi & 63;
            *(uint32_t*)(smem + SM_BH + r * (AS * 2) + c * 4) = __ldg(&gh[r * 64 + c]);
            *(uint32_t*)(smem + SM_BL + r * (AS * 2) + c * 4) = __ldg(&gl[r * 64 + c]);
        }
    }
    __syncthreads();

    const int g = lane >> 2, t = lane & 3;
    const int mOff = (wid & 3) * 32;
    const int nOff = (wid >> 2) * 64;

    float acc[2][8][4];
#pragma unroll
    for (int i = 0; i < 2; i++)
#pragma unroll
        for (int j = 0; j < 8; j++)
#pragma unroll
            for (int q = 0; q < 4; q++) acc[i][j][q] = 0.0f;

#pragma unroll
    for (int ks = 0; ks < 8; ks++) {
        int k0 = ks * 16;
        uint32_t ah[2][4], al[2][4];
#pragma unroll
        for (int i = 0; i < 2; i++) {
            int r0 = mOff + i * 16 + g;
            const char* pah = smem + SM_AH;
            const char* pal = smem + SM_AL;
            ah[i][0] = *(const uint32_t*)(pah + (r0)     * (AS * 2) + (k0 + t * 2) * 2);
            ah[i][1] = *(const uint32_t*)(pah + (r0 + 8) * (AS * 2) + (k0 + t * 2) * 2);
            ah[i][2] = *(const uint32_t*)(pah + (r0)     * (AS * 2) + (k0 + t * 2 + 8) * 2);
            ah[i][3] = *(const uint32_t*)(pah + (r0 + 8) * (AS * 2) + (k0 + t * 2 + 8) * 2);
            al[i][0] = *(const uint32_t*)(pal + (r0)     * (AS * 2) + (k0 + t * 2) * 2);
            al[i][1] = *(const uint32_t*)(pal + (r0 + 8) * (AS * 2) + (k0 + t * 2) * 2);
            al[i][2] = *(const uint32_t*)(pal + (r0)     * (AS * 2) + (k0 + t * 2 + 8) * 2);
            al[i][3] = *(const uint32_t*)(pal + (r0 + 8) * (AS * 2) + (k0 + t * 2 + 8) * 2);
        }
#pragma unroll
        for (int j = 0; j < 8; j++) {
            int n0 = nOff + j * 8 + g;
            uint32_t bh0 = *(const uint32_t*)(smem + SM_BH + n0 * (AS * 2) + (k0 + t * 2) * 2);
            uint32_t bh1 = *(const uint32_t*)(smem + SM_BH + n0 * (AS * 2) + (k0 + t * 2 + 8) * 2);
            uint32_t bl0 = *(const uint32_t*)(smem + SM_BL + n0 * (AS * 2) + (k0 + t * 2) * 2);
            uint32_t bl1 = *(const uint32_t*)(smem + SM_BL + n0 * (AS * 2) + (k0 + t * 2 + 8) * 2);
#pragma unroll
            for (int i = 0; i < 2; i++) {
                mma_bf16(acc[i][j], ah[i][0], ah[i][1], ah[i][2], ah[i][3], bh0, bh1);
                mma_bf16(acc[i][j], ah[i][0], ah[i][1], ah[i][2], ah[i][3], bl0, bl1);
                mma_bf16(acc[i][j], al[i][0], al[i][1], al[i][2], al[i][3], bh0, bh1);
            }
        }
    }

#pragma unroll
    for (int i = 0; i < 2; i++) {
#pragma unroll
        for (int j = 0; j < 8; j++) {
            int row = rowBase + mOff + i * 16 + g;
            int col = nOff + j * 8 + t * 2;
            if (row < M)
                *(float2*)(H + (size_t)row * HID + col) = make_float2(acc[i][j][0], acc[i][j][1]);
            if (row + 8 < M)
                *(float2*)(H + (size_t)(row + 8) * HID + col) = make_float2(acc[i][j][2], acc[i][j][3]);
        }
    }
}

// ---------------- gather core (returns activated node vector) ----------------
__device__ __forceinline__ float4 gather_node(
    const float* __restrict__ H, const int* __restrict__ rowptr,
    const int2* __restrict__ csr, const float* __restrict__ dinv,
    const float* __restrict__ bias, int n, int lane)
{
    float di = __ldg(dinv + n);
    float sl = di * di;
    float4 a = *(const float4*)(H + (size_t)n * HID + lane * 4);
    float4 acc = make_float4(a.x * sl, a.y * sl, a.z * sl, a.w * sl);

    int i   = __ldg(rowptr + n);
    int end = __ldg(rowptr + n + 1);

    for (; i + 4 <= end; i += 4) {
        int2 e0 = __ldg(csr + i + 0);
        int2 e1 = __ldg(csr + i + 1);
        int2 e2 = __ldg(csr + i + 2);
        int2 e3 = __ldg(csr + i + 3);
        float c0 = __int_as_float(e0.y), c1 = __int_as_float(e1.y);
        float c2 = __int_as_float(e2.y), c3 = __int_as_float(e3.y);
        float4 v0 = *(const float4*)(H + (size_t)e0.x * HID + lane * 4);
        float4 v1 = *(const float4*)(H + (size_t)e1.x * HID + lane * 4);
        float4 v2 = *(const float4*)(H + (size_t)e2.x * HID + lane * 4);
        float4 v3 = *(const float4*)(H + (size_t)e3.x * HID + lane * 4);
        acc.x = fmaf(c0, v0.x, acc.x); acc.y = fmaf(c0, v0.y, acc.y);
        acc.z = fmaf(c0, v0.z, acc.z); acc.w = fmaf(c0, v0.w, acc.w);
        acc.x = fmaf(c1, v1.x, acc.x); acc.y = fmaf(c1, v1.y, acc.y);
        acc.z = fmaf(c1, v1.z, acc.z); acc.w = fmaf(c1, v1.w, acc.w);
        acc.x = fmaf(c2, v2.x, acc.x); acc.y = fmaf(c2, v2.y, acc.y);
        acc.z = fmaf(c2, v2.z, acc.z); acc.w = fmaf(c2, v2.w, acc.w);
        acc.x = fmaf(c3, v3.x, acc.x); acc.y = fmaf(c3, v3.y, acc.y);
        acc.z = fmaf(c3, v3.z, acc.z); acc.w = fmaf(c3, v3.w, acc.w);
    }
    for (; i < end; i++) {
        int2 e = __ldg(csr + i);
        float c = __int_as_float(e.y);
        float4 v = *(const float4*)(H + (size_t)e.x * HID + lane * 4);
        acc.x = fmaf(c, v.x, acc.x); acc.y = fmaf(c, v.y, acc.y);
        acc.z = fmaf(c, v.z, acc.z); acc.w = fmaf(c, v.w, acc.w);
    }

    float4 b = *(const float4*)(bias + lane * 4);
    acc.x = leaky(acc.x + b.x);
    acc.y = leaky(acc.y + b.y);
    acc.z = leaky(acc.z + b.z);
    acc.w = leaky(acc.w + b.w);
    return acc;
}

// layer-1 gather: write activated features to OUT
__global__ __launch_bounds__(256) void gather_kernel(
    const float* __restrict__ H, float* __restrict__ OUT,
    const int* __restrict__ rowptr, const int2* __restrict__ csr,
    const float* __restrict__ dinv, const float* __restrict__ bias)
{
    int n = blockIdx.x * 8 + (threadIdx.x >> 5);
    int lane = threadIdx.x & 31;
    if (n >= N_NODES) return;
    float4 acc = gather_node(H, rowptr, csr, dinv, bias, n, lane);
    *(float4*)(OUT + (size_t)n * HID + lane * 4) = acc;
}

// layer-2 gather fused with mean-pool accumulation
__global__ __launch_bounds__(256) void gather_pool_kernel(
    const float* __restrict__ H,
    const int* __restrict__ rowptr, const int2* __restrict__ csr,
    const float* __restrict__ dinv, const float* __restrict__ bias,
    const int* __restrict__ batch, float* __restrict__ pool, float* __restrict__ cnt)
{
    int n = blockIdx.x * 8 + (threadIdx.x >> 5);
    int lane = threadIdx.x & 31;
    if (n >= N_NODES) return;
    float4 acc = gather_node(H, rowptr, csr, dinv, bias, n, lane);
    int g = __ldg(batch + n);
    red_add_v4(pool + (size_t)g * HID + lane * 4, acc.x, acc.y, acc.z, acc.w);
    if (lane == 0) atomicAdd(&cnt[g], 1.0f);
}

// ---------------- finalize ----------------
__global__ void finalize_kernel(const float* __restrict__ pool, const float* __restrict__ cnt,
                                float* __restrict__ out)
{
    int i = blockIdx.x * blockDim.x + threadIdx.x;
    if (i >= N_GRAPHS * HID) return;
    int g = i >> 7;
    out[i] = pool[i] / fmaxf(cnt[g], 1.0f);
}

// ---------------- launch ----------------
extern "C" void kernel_launch(void* const* d_in, const int* in_sizes, int n_in,
                              void* d_out, int out_size)
{
    const float* drug_x = (const float*)d_in[0];
    const float* W1     = (const float*)d_in[1];
    const float* b1     = (const float*)d_in[2];
    const float* W2     = (const float*)d_in[3];
    const float* b2     = (const float*)d_in[4];
    const int*   eidx   = (const int*)d_in[5];
    const int*   batch  = (const int*)d_in[6];
    float* out = (float*)d_out;

    const int* src = eidx;
    const int* dst = eidx + N_EDGES;

    float *bufA, *bufC, *dinv, *pool, *cnt;
    int *count, *rowptr, *cursor, *blocksum, *blockoff;
    int2* csr;
    __nv_bfloat16 *w1h, *w1l, *w2h, *w2l;
    cudaGetSymbolAddress((void**)&bufA, g_bufA);
    cudaGetSymbolAddress((void**)&bufC, g_bufC);
    cudaGetSymbolAddress((void**)&dinv, g_dinv);
    cudaGetSymbolAddress((void**)&pool, g_pool);
    cudaGetSymbolAddress((void**)&cnt,  g_cnt);
    cudaGetSymbolAddress((void**)&count,  g_count);
    cudaGetSymbolAddress((void**)&rowptr, g_rowptr);
    cudaGetSymbolAddress((void**)&cursor, g_cursor);
    cudaGetSymbolAddress((void**)&csr, g_csr);
    cudaGetSymbolAddress((void**)&blocksum, g_blocksum);
    cudaGetSymbolAddress((void**)&blockoff, g_blockoff);
    cudaGetSymbolAddress((void**)&w1h, g_wt1_hi);
    cudaGetSymbolAddress((void**)&w1l, g_wt1_lo);
    cudaGetSymbolAddress((void**)&w2h, g_wt2_hi);
    cudaGetSymbolAddress((void**)&w2l, g_wt2_lo);

    cudaFuncSetAttribute(gemm_mma_kernel, cudaFuncAttributeMaxDynamicSharedMemorySize,
                         SM_GEMM_TOTAL);

    const int T = 256;
    int gemm_blocks = (N_NODES + 127) / 128;   // 391
    int gath_blocks = (N_NODES + 7) / 8;

    // CSR build + W prep
    init_kernel<<<(N_GRAPHS * HID + T - 1) / T, T>>>(pool, cnt, count);
    wprep_kernel<<<(HID * HID + T - 1) / T, T>>>(W1, w1h, w1l);
    wprep_kernel<<<(HID * HID + T - 1) / T, T>>>(W2, w2h, w2l);
    hist_kernel<<<(N_EDGES / 4 + T - 1) / T, T>>>(dst, count);
    blocksum_dinv_kernel<<<SCAN_B, SCAN_T>>>(count, blocksum, dinv);
    scanblock_kernel<<<1, 256>>>(blocksum, blockoff);
    writeptr_kernel<<<SCAN_B, SCAN_T>>>(count, blockoff, rowptr, cursor);
    fill_kernel<<<(N_EDGES + T - 1) / T, T>>>(src, dst, dinv, cursor, csr);

    // layer 1
    gemm_mma_kernel<<<gemm_blocks, T, SM_GEMM_TOTAL>>>(drug_x, w1h, w1l, bufA, N_NODES);
    gather_kernel<<<gath_blocks, T>>>(bufA, bufC, rowptr, csr, dinv, b1);

    // layer 2 (gather fused with mean-pool accumulation)
    gemm_mma_kernel<<<gemm_blocks, T, SM_GEMM_TOTAL>>>(bufC, w2h, w2l, bufA, N_NODES);
    gather_pool_kernel<<<gath_blocks, T>>>(bufA, rowptr, csr, dinv, b2, batch, pool, cnt);

    finalize_kernel<<<(N_GRAPHS * HID + T - 1) / T, T>>>(pool, cnt, out);
}

// round 8
// speedup vs baseline: 2.1342x; 1.1344x over previous
#include <cuda_runtime.h>
#include <cuda_bf16.h>
#include <cuda_fp16.h>
#include <cstdint>

#define N_NODES 50000
#define N_EDGES 600000
#define N_GRAPHS 1000
#define HID 128
#define NEG_SLOPE 0.01f

#define SCAN_T 256
#define SCAN_B ((N_NODES + SCAN_T - 1) / SCAN_T)   // 196

// ---------------- scratch (static device globals; no allocation) ----------------
__device__ __half g_bufH[(size_t)N_NODES * HID];   // GEMM output, fp16 (12.8 MB)
__device__ float  g_bufC[(size_t)N_NODES * HID];   // layer-1 activated output, fp32
__device__ float  g_dinv[N_NODES];
__device__ float  g_pool[N_GRAPHS * HID];
__device__ float  g_cnt[N_GRAPHS];
__device__ int    g_count[N_NODES];
__device__ int    g_rowptr[N_NODES + 1];
__device__ int    g_cursor[N_NODES];
__device__ int2   g_csr[N_EDGES];                  // {src, coef-as-int}
__device__ int    g_blocksum[SCAN_B];
__device__ int    g_blockoff[SCAN_B];
// W^T bf16 hi/lo images [N=128][K=128] row-major (both layers)
__device__ __nv_bfloat16 g_wt_hi[2][HID * HID];
__device__ __nv_bfloat16 g_wt_lo[2][HID * HID];

// ---------------- helpers ----------------
__device__ __forceinline__ float leaky(float x) {
    return x > 0.0f ? x : NEG_SLOPE * x;
}

__device__ __forceinline__ void red_add_v4(float* addr, float a, float b, float c, float d) {
    asm volatile("red.global.add.v4.f32 [%0], {%1, %2, %3, %4};"
                 :: "l"(addr), "f"(a), "f"(b), "f"(c), "f"(d) : "memory");
}

// load 4 consecutive halfs -> float4
__device__ __forceinline__ float4 ld_half4(const __half* p) {
    uint2 u = __ldg((const uint2*)p);
    __half2 h0 = *reinterpret_cast<__half2*>(&u.x);
    __half2 h1 = *reinterpret_cast<__half2*>(&u.y);
    float2 f0 = __half22float2(h0);
    float2 f1 = __half22float2(h1);
    return make_float4(f0.x, f0.y, f1.x, f1.y);
}

// portable bf16 warp MMA: D(16x8,f32) += A(16x16,bf16) * B(16x8,bf16)
__device__ __forceinline__ void mma_bf16(float* d,
                                         uint32_t a0, uint32_t a1, uint32_t a2, uint32_t a3,
                                         uint32_t b0, uint32_t b1) {
    asm volatile("mma.sync.aligned.m16n8k16.row.col.f32.bf16.bf16.f32 "
                 "{%0,%1,%2,%3}, {%4,%5,%6,%7}, {%8,%9}, {%0,%1,%2,%3};"
                 : "+f"(d[0]), "+f"(d[1]), "+f"(d[2]), "+f"(d[3])
                 : "r"(a0), "r"(a1), "r"(a2), "r"(a3), "r"(b0), "r"(b1));
}

// ---------------- init: zero pool/cnt/count ----------------
__global__ void init_kernel(float* pool, float* cnt, int* count) {
    int i = blockIdx.x * blockDim.x + threadIdx.x;
    if (i < N_GRAPHS * HID) pool[i] = 0.0f;
    if (i < N_NODES) count[i] = 0;
    if (i < N_GRAPHS) cnt[i] = 0.0f;
}

// ---------------- degree histogram over dst ----------------
__global__ void hist_kernel(const int* __restrict__ dst, int* __restrict__ count) {
    int t = blockIdx.x * blockDim.x + threadIdx.x;
    if (t >= N_EDGES / 4) return;
    int4 d = __ldg((const int4*)dst + t);
    atomicAdd(&count[d.x], 1);
    atomicAdd(&count[d.y], 1);
    atomicAdd(&count[d.z], 1);
    atomicAdd(&count[d.w], 1);
}

// ---------------- scan phase 1 + dinv ----------------
__global__ __launch_bounds__(SCAN_T) void blocksum_dinv_kernel(const int* __restrict__ count,
                                                               int* __restrict__ blocksum,
                                                               float* __restrict__ dinv)
{
    __shared__ int warpsum[SCAN_T / 32];
    int i = blockIdx.x * SCAN_T + threadIdx.x;
    int v = (i < N_NODES) ? count[i] : 0;
    if (i < N_NODES) dinv[i] = rsqrtf((float)v + 1.0f);
    int s = v;
#pragma unroll
    for (int off = 16; off > 0; off >>= 1)
        s += __shfl_down_sync(0xffffffffu, s, off);
    if ((threadIdx.x & 31) == 0) warpsum[threadIdx.x >> 5] = s;
    __syncthreads();
    if (threadIdx.x < SCAN_T / 32) {
        int w = warpsum[threadIdx.x];
#pragma unroll
        for (int off = SCAN_T / 64; off > 0; off >>= 1)
            w += __shfl_down_sync(0xffu, w, off);
        if (threadIdx.x == 0) blocksum[blockIdx.x] = w;
    }
}

__global__ __launch_bounds__(256) void scanblock_kernel(const int* __restrict__ blocksum,
                                                        int* __restrict__ blockoff)
{
    __shared__ int warptot[8];
    int t = threadIdx.x;
    int v = (t < SCAN_B) ? blocksum[t] : 0;
    int lane = t & 31, w = t >> 5;
    int x = v;
#pragma unroll
    for (int off = 1; off < 32; off <<= 1) {
        int y = __shfl_up_sync(0xffffffffu, x, off);
        if (lane >= off) x += y;
    }
    if (lane == 31) warptot[w] = x;
    __syncthreads();
    if (t < 8) {
        int s = warptot[t];
#pragma unroll
        for (int off = 1; off < 8; off <<= 1) {
            int y = __shfl_up_sync(0xffu, s, off);
            if (t >= off) s += y;
        }
        warptot[t] = s;
    }
    __syncthreads();
    int excl = x - v + (w > 0 ? warptot[w - 1] : 0);
    if (t < SCAN_B) blockoff[t] = excl;
}

__global__ __launch_bounds__(SCAN_T) void writeptr_kernel(const int* __restrict__ count,
                                                          const int* __restrict__ blockoff,
                                                          int* __restrict__ rowptr,
                                                          int* __restrict__ cursor)
{
    __shared__ int warptot[SCAN_T / 32];
    int i = blockIdx.x * SCAN_T + threadIdx.x;
    int v = (i < N_NODES) ? count[i] : 0;
    int lane = threadIdx.x & 31, w = threadIdx.x >> 5;
    int x = v;
#pragma unroll
    for (int off = 1; off < 32; off <<= 1) {
        int y = __shfl_up_sync(0xffffffffu, x, off);
        if (lane >= off) x += y;
    }
    if (lane == 31) warptot[w] = x;
    __syncthreads();
    if (threadIdx.x < SCAN_T / 32) {
        int s = warptot[threadIdx.x];
#pragma unroll
        for (int off = 1; off < SCAN_T / 32; off <<= 1) {
            int y = __shfl_up_sync(0xffu, s, off);
            if ((int)threadIdx.x >= off) s += y;
        }
        warptot[threadIdx.x] = s;
    }
    __syncthreads();
    int excl = x - v + (w > 0 ? warptot[w - 1] : 0) + blockoff[blockIdx.x];
    if (i < N_NODES) {
        rowptr[i] = excl;
        cursor[i] = excl;
    }
    if (i == 0) rowptr[N_NODES] = N_EDGES;
}

// ---------------- fill CSR (packed int2) ----------------
__global__ void fill_kernel(const int* __restrict__ src, const int* __restrict__ dst,
                            const float* __restrict__ dinv, int* __restrict__ cursor,
                            int2* __restrict__ csr)
{
    int e = blockIdx.x * blockDim.x + threadIdx.x;
    if (e >= N_EDGES) return;
    int s = __ldg(src + e);
    int d = __ldg(dst + e);
    int p = atomicAdd(&cursor[d], 1);
    float coef = __ldg(dinv + s) * __ldg(dinv + d);
    csr[p] = make_int2(s, __float_as_int(coef));
}

// ---------------- W prep (both layers in one launch; blockIdx.y = layer) ----------------
__global__ void wprep_kernel(const float* __restrict__ W1, const float* __restrict__ W2,
                             __nv_bfloat16* __restrict__ wt_hi,
                             __nv_bfloat16* __restrict__ wt_lo)
{
    int i = blockIdx.x * blockDim.x + threadIdx.x;
    if (i >= HID * HID) return;
    int layer = blockIdx.y;
    const float* W = layer ? W2 : W1;
    int n = i & 127, k = i >> 7;
    float v = W[i];
    __nv_bfloat16 h = __float2bfloat16(v);
    __nv_bfloat16 l = __float2bfloat16(v - __bfloat162float(h));
    wt_hi[layer * HID * HID + n * HID + k] = h;
    wt_lo[layer * HID * HID + n * HID + k] = l;
}

// ---------------- warp-MMA GEMM: H(fp16) = X*W (split-bf16, fp32 accum) ----------------
#define AS 132
#define SM_AH 0
#define SM_AL (SM_AH + 128 * AS * 2)
#define SM_BH (SM_AL + 128 * AS * 2)
#define SM_BL (SM_BH + 128 * AS * 2)
#define SM_GEMM_TOTAL (SM_BL + 128 * AS * 2)   // 135168 B

__global__ __launch_bounds__(256) void gemm_mma_kernel(
    const float* __restrict__ X,
    const __nv_bfloat16* __restrict__ wt_hi,
    const __nv_bfloat16* __restrict__ wt_lo,
    __half* __restrict__ H, int M)
{
    extern __shared__ char smem[];
    const int tid = threadIdx.x;
    const int wid = tid >> 5;
    const int lane = tid & 31;
    const int rowBase = blockIdx.x * 128;

    {
        int row = tid >> 1;
        int half_ = tid & 1;
        int gr = rowBase + row;
        const float4* xr = (const float4*)(X + (size_t)gr * HID + half_ * 64);
        char* ah = smem + SM_AH + row * (AS * 2) + half_ * 128;
        char* al = smem + SM_AL + row * (AS * 2) + half_ * 128;
#pragma unroll
        for (int k4 = 0; k4 < 16; k4++) {
            float4 v = (gr < M) ? __ldg(&xr[k4]) : make_float4(0.f, 0.f, 0.f, 0.f);
            __nv_bfloat16 h0 = __float2bfloat16(v.x), h1 = __float2bfloat16(v.y);
            __nv_bfloat16 h2 = __float2bfloat16(v.z), h3 = __float2bfloat16(v.w);
            __nv_bfloat16 l0 = __float2bfloat16(v.x - __bfloat162float(h0));
            __nv_bfloat16 l1 = __float2bfloat16(v.y - __bfloat162float(h1));
            __nv_bfloat16 l2 = __float2bfloat16(v.z - __bfloat162float(h2));
            __nv_bfloat16 l3 = __float2bfloat16(v.w - __bfloat162float(h3));
            uint2 hp, lp;
            hp.x = (uint32_t)__bfloat16_as_ushort(h0) | ((uint32_t)__bfloat16_as_ushort(h1) << 16);
            hp.y = (uint32_t)__bfloat16_as_ushort(h2) | ((uint32_t)__bfloat16_as_ushort(h3) << 16);
            lp.x = (uint32_t)__bfloat16_as_ushort(l0) | ((uint32_t)__bfloat16_as_ushort(l1) << 16);
            lp.y = (uint32_t)__bfloat16_as_ushort(l2) | ((uint32_t)__bfloat16_as_ushort(l3) << 16);
            *(uint2*)(ah + k4 * 8) = hp;
            *(uint2*)(al + k4 * 8) = lp;
        }
    }
    {
        const uint32_t* gh = (const uint32_t*)wt_hi;
        const uint32_t* gl = (const uint32_t*)wt_lo;
#pragma unroll
        for (int w = 0; w < 32; w++) {
            int wi = tid + w * 256;
            int r = wi >> 6, c = wi & 63;
            *(uint32_t*)(smem + SM_BH + r * (AS * 2) + c * 4) = __ldg(&gh[r * 64 + c]);
            *(uint32_t*)(smem + SM_BL + r * (AS * 2) + c * 4) = __ldg(&gl[r * 64 + c]);
        }
    }
    __syncthreads();

    const int g = lane >> 2, t = lane & 3;
    const int mOff = (wid & 3) * 32;
    const int nOff = (wid >> 2) * 64;

    float acc[2][8][4];
#pragma unroll
    for (int i = 0; i < 2; i++)
#pragma unroll
        for (int j = 0; j < 8; j++)
#pragma unroll
            for (int q = 0; q < 4; q++) acc[i][j][q] = 0.0f;

#pragma unroll
    for (int ks = 0; ks < 8; ks++) {
        int k0 = ks * 16;
        uint32_t ah[2][4], al[2][4];
#pragma unroll
        for (int i = 0; i < 2; i++) {
            int r0 = mOff + i * 16 + g;
            const char* pah = smem + SM_AH;
            const char* pal = smem + SM_AL;
            ah[i][0] = *(const uint32_t*)(pah + (r0)     * (AS * 2) + (k0 + t * 2) * 2);
            ah[i][1] = *(const uint32_t*)(pah + (r0 + 8) * (AS * 2) + (k0 + t * 2) * 2);
            ah[i][2] = *(const uint32_t*)(pah + (r0)     * (AS * 2) + (k0 + t * 2 + 8) * 2);
            ah[i][3] = *(const uint32_t*)(pah + (r0 + 8) * (AS * 2) + (k0 + t * 2 + 8) * 2);
            al[i][0] = *(const uint32_t*)(pal + (r0)     * (AS * 2) + (k0 + t * 2) * 2);
            al[i][1] = *(const uint32_t*)(pal + (r0 + 8) * (AS * 2) + (k0 + t * 2) * 2);
            al[i][2] = *(const uint32_t*)(pal + (r0)     * (AS * 2) + (k0 + t * 2 + 8) * 2);
            al[i][3] = *(const uint32_t*)(pal + (r0 + 8) * (AS * 2) + (k0 + t * 2 + 8) * 2);
        }
#pragma unroll
        for (int j = 0; j < 8; j++) {
            int n0 = nOff + j * 8 + g;
            uint32_t bh0 = *(const uint32_t*)(smem + SM_BH + n0 * (AS * 2) + (k0 + t * 2) * 2);
            uint32_t bh1 = *(const uint32_t*)(smem + SM_BH + n0 * (AS * 2) + (k0 + t * 2 + 8) * 2);
            uint32_t bl0 = *(const uint32_t*)(smem + SM_BL + n0 * (AS * 2) + (k0 + t * 2) * 2);
            uint32_t bl1 = *(const uint32_t*)(smem + SM_BL + n0 * (AS * 2) + (k0 + t * 2 + 8) * 2);
#pragma unroll
            for (int i = 0; i < 2; i++) {
                mma_bf16(acc[i][j], ah[i][0], ah[i][1], ah[i][2], ah[i][3], bh0, bh1);
                mma_bf16(acc[i][j], ah[i][0], ah[i][1], ah[i][2], ah[i][3], bl0, bl1);
                mma_bf16(acc[i][j], al[i][0], al[i][1], al[i][2], al[i][3], bh0, bh1);
            }
        }
    }

    // epilogue: fp16 output
#pragma unroll
    for (int i = 0; i < 2; i++) {
#pragma unroll
        for (int j = 0; j < 8; j++) {
            int row = rowBase + mOff + i * 16 + g;
            int col = nOff + j * 8 + t * 2;
            if (row < M)
                *(__half2*)(H + (size_t)row * HID + col) =
                    __floats2half2_rn(acc[i][j][0], acc[i][j][1]);
            if (row + 8 < M)
                *(__half2*)(H + (size_t)(row + 8) * HID + col) =
                    __floats2half2_rn(acc[i][j][2], acc[i][j][3]);
        }
    }
}

// ---------------- gather core (fp16 H) ----------------
__device__ __forceinline__ float4 gather_node(
    const __half* __restrict__ H, const int* __restrict__ rowptr,
    const int2* __restrict__ csr, const float* __restrict__ dinv,
    const float* __restrict__ bias, int n, int lane)
{
    float di = __ldg(dinv + n);
    float sl = di * di;
    float4 a = ld_half4(H + (size_t)n * HID + lane * 4);
    float4 acc = make_float4(a.x * sl, a.y * sl, a.z * sl, a.w * sl);

    int i   = __ldg(rowptr + n);
    int end = __ldg(rowptr + n + 1);

    for (; i + 4 <= end; i += 4) {
        int2 e0 = __ldg(csr + i + 0);
        int2 e1 = __ldg(csr + i + 1);
        int2 e2 = __ldg(csr + i + 2);
        int2 e3 = __ldg(csr + i + 3);
        float c0 = __int_as_float(e0.y), c1 = __int_as_float(e1.y);
        float c2 = __int_as_float(e2.y), c3 = __int_as_float(e3.y);
        float4 v0 = ld_half4(H + (size_t)e0.x * HID + lane * 4);
        float4 v1 = ld_half4(H + (size_t)e1.x * HID + lane * 4);
        float4 v2 = ld_half4(H + (size_t)e2.x * HID + lane * 4);
        float4 v3 = ld_half4(H + (size_t)e3.x * HID + lane * 4);
        acc.x = fmaf(c0, v0.x, acc.x); acc.y = fmaf(c0, v0.y, acc.y);
        acc.z = fmaf(c0, v0.z, acc.z); acc.w = fmaf(c0, v0.w, acc.w);
        acc.x = fmaf(c1, v1.x, acc.x); acc.y = fmaf(c1, v1.y, acc.y);
        acc.z = fmaf(c1, v1.z, acc.z); acc.w = fmaf(c1, v1.w, acc.w);
        acc.x = fmaf(c2, v2.x, acc.x); acc.y = fmaf(c2, v2.y, acc.y);
        acc.z = fmaf(c2, v2.z, acc.z); acc.w = fmaf(c2, v2.w, acc.w);
        acc.x = fmaf(c3, v3.x, acc.x); acc.y = fmaf(c3, v3.y, acc.y);
        acc.z = fmaf(c3, v3.z, acc.z); acc.w = fmaf(c3, v3.w, acc.w);
    }
    for (; i < end; i++) {
        int2 e = __ldg(csr + i);
        float c = __int_as_float(e.y);
        float4 v = ld_half4(H + (size_t)e.x * HID + lane * 4);
        acc.x = fmaf(c, v.x, acc.x); acc.y = fmaf(c, v.y, acc.y);
        acc.z = fmaf(c, v.z, acc.z); acc.w = fmaf(c, v.w, acc.w);
    }

    float4 b = *(const float4*)(bias + lane * 4);
    acc.x = leaky(acc.x + b.x);
    acc.y = leaky(acc.y + b.y);
    acc.z = leaky(acc.z + b.z);
    acc.w = leaky(acc.w + b.w);
    return acc;
}

// layer-1 gather: write activated fp32 features
__global__ __launch_bounds__(256) void gather_kernel(
    const __half* __restrict__ H, float* __restrict__ OUT,
    const int* __restrict__ rowptr, const int2* __restrict__ csr,
    const float* __restrict__ dinv, const float* __restrict__ bias)
{
    int n = blockIdx.x * 8 + (threadIdx.x >> 5);
    int lane = threadIdx.x & 31;
    if (n >= N_NODES) return;
    float4 acc = gather_node(H, rowptr, csr, dinv, bias, n, lane);
    *(float4*)(OUT + (size_t)n * HID + lane * 4) = acc;
}

// layer-2 gather fused with mean-pool accumulation
__global__ __launch_bounds__(256) void gather_pool_kernel(
    const __half* __restrict__ H,
    const int* __restrict__ rowptr, const int2* __restrict__ csr,
    const float* __restrict__ dinv, const float* __restrict__ bias,
    const int* __restrict__ batch, float* __restrict__ pool, float* __restrict__ cnt)
{
    int n = blockIdx.x * 8 + (threadIdx.x >> 5);
    int lane = threadIdx.x & 31;
    if (n >= N_NODES) return;
    float4 acc = gather_node(H, rowptr, csr, dinv, bias, n, lane);
    int g = __ldg(batch + n);
    red_add_v4(pool + (size_t)g * HID + lane * 4, acc.x, acc.y, acc.z, acc.w);
    if (lane == 0) atomicAdd(&cnt[g], 1.0f);
}

// ---------------- finalize ----------------
__global__ void finalize_kernel(const float* __restrict__ pool, const float* __restrict__ cnt,
                                float* __restrict__ out)
{
    int i = blockIdx.x * blockDim.x + threadIdx.x;
    if (i >= N_GRAPHS * HID) return;
    int g = i >> 7;
    out[i] = pool[i] / fmaxf(cnt[g], 1.0f);
}

// ---------------- launch ----------------
extern "C" void kernel_launch(void* const* d_in, const int* in_sizes, int n_in,
                              void* d_out, int out_size)
{
    const float* drug_x = (const float*)d_in[0];
    const float* W1     = (const float*)d_in[1];
    const float* b1     = (const float*)d_in[2];
    const float* W2     = (const float*)d_in[3];
    const float* b2     = (const float*)d_in[4];
    const int*   eidx   = (const int*)d_in[5];
    const int*   batch  = (const int*)d_in[6];
    float* out = (float*)d_out;

    const int* src = eidx;
    const int* dst = eidx + N_EDGES;

    __half* bufH;
    float *bufC, *dinv, *pool, *cnt;
    int *count, *rowptr, *cursor, *blocksum, *blockoff;
    int2* csr;
    __nv_bfloat16 *wth, *wtl;
    cudaGetSymbolAddress((void**)&bufH, g_bufH);
    cudaGetSymbolAddress((void**)&bufC, g_bufC);
    cudaGetSymbolAddress((void**)&dinv, g_dinv);
    cudaGetSymbolAddress((void**)&pool, g_pool);
    cudaGetSymbolAddress((void**)&cnt,  g_cnt);
    cudaGetSymbolAddress((void**)&count,  g_count);
    cudaGetSymbolAddress((void**)&rowptr, g_rowptr);
    cudaGetSymbolAddress((void**)&cursor, g_cursor);
    cudaGetSymbolAddress((void**)&csr, g_csr);
    cudaGetSymbolAddress((void**)&blocksum, g_blocksum);
    cudaGetSymbolAddress((void**)&blockoff, g_blockoff);
    cudaGetSymbolAddress((void**)&wth, g_wt_hi);
    cudaGetSymbolAddress((void**)&wtl, g_wt_lo);

    cudaFuncSetAttribute(gemm_mma_kernel, cudaFuncAttributeMaxDynamicSharedMemorySize,
                         SM_GEMM_TOTAL);

    const int T = 256;
    int gemm_blocks = (N_NODES + 127) / 128;   // 391
    int gath_blocks = (N_NODES + 7) / 8;

    // CSR build + W prep
    init_kernel<<<(N_GRAPHS * HID + T - 1) / T, T>>>(pool, cnt, count);
    {
        dim3 wgrid((HID * HID + T - 1) / T, 2);
        wprep_kernel<<<wgrid, T>>>(W1, W2, wth, wtl);
    }
    hist_kernel<<<(N_EDGES / 4 + T - 1) / T, T>>>(dst, count);
    blocksum_dinv_kernel<<<SCAN_B, SCAN_T>>>(count, blocksum, dinv);
    scanblock_kernel<<<1, 256>>>(blocksum, blockoff);
    writeptr_kernel<<<SCAN_B, SCAN_T>>>(count, blockoff, rowptr, cursor);
    fill_kernel<<<(N_EDGES + T - 1) / T, T>>>(src, dst, dinv, cursor, csr);

    // layer 1
    gemm_mma_kernel<<<gemm_blocks, T, SM_GEMM_TOTAL>>>(drug_x, wth, wtl, bufH, N_NODES);
    gather_kernel<<<gath_blocks, T>>>(bufH, bufC, rowptr, csr, dinv, b1);

    // layer 2 (gather fused with mean-pool accumulation)
    gemm_mma_kernel<<<gemm_blocks, T, SM_GEMM_TOTAL>>>(bufC, wth + HID * HID, wtl + HID * HID,
                                                       bufH, N_NODES);
    gather_pool_kernel<<<gath_blocks, T>>>(bufH, rowptr, csr, dinv, b2, batch, pool, cnt);

    finalize_kernel<<<(N_GRAPHS * HID + T - 1) / T, T>>>(pool, cnt, out);
}

// round 9
// speedup vs baseline: 2.1579x; 1.0111x over previous
#include <cuda_runtime.h>
#include <cuda_bf16.h>
#include <cuda_fp16.h>
#include <cstdint>

#define N_NODES 50000
#define N_EDGES 600000
#define N_GRAPHS 1000
#define HID 128
#define NEG_SLOPE 0.01f

#define SCAN_T 256
#define SCAN_B ((N_NODES + SCAN_T - 1) / SCAN_T)   // 196

// ---------------- scratch (static device globals; no allocation) ----------------
__device__ __half g_bufH[(size_t)N_NODES * HID];   // GEMM output, fp16
__device__ __half g_bufC[(size_t)N_NODES * HID];   // layer-1 activated output, fp16
__device__ float  g_dinv[N_NODES];
__device__ float  g_pool[N_GRAPHS * HID];
__device__ float  g_cnt[N_GRAPHS];
__device__ int    g_count[N_NODES];
__device__ int    g_rowptr[N_NODES + 1];
__device__ int    g_cursor[N_NODES];
__device__ int2   g_csr[N_EDGES];                  // {src, coef-as-int}
__device__ unsigned long long g_tilestate[SCAN_B]; // (state<<32)|value; 0=inv,1=agg,2=prefix
// W^T bf16 hi/lo images [N=128][K=128] row-major (both layers)
__device__ __nv_bfloat16 g_wt_hi[2][HID * HID];
__device__ __nv_bfloat16 g_wt_lo[2][HID * HID];

// ---------------- helpers ----------------
__device__ __forceinline__ float leaky(float x) {
    return x > 0.0f ? x : NEG_SLOPE * x;
}

__device__ __forceinline__ void red_add_v4(float* addr, float a, float b, float c, float d) {
    asm volatile("red.global.add.v4.f32 [%0], {%1, %2, %3, %4};"
                 :: "l"(addr), "f"(a), "f"(b), "f"(c), "f"(d) : "memory");
}

__device__ __forceinline__ float4 ld_half4(const __half* p) {
    uint2 u = __ldg((const uint2*)p);
    __half2 h0 = *reinterpret_cast<__half2*>(&u.x);
    __half2 h1 = *reinterpret_cast<__half2*>(&u.y);
    float2 f0 = __half22float2(h0);
    float2 f1 = __half22float2(h1);
    return make_float4(f0.x, f0.y, f1.x, f1.y);
}

__device__ __forceinline__ void mma_bf16(float* d,
                                         uint32_t a0, uint32_t a1, uint32_t a2, uint32_t a3,
                                         uint32_t b0, uint32_t b1) {
    asm volatile("mma.sync.aligned.m16n8k16.row.col.f32.bf16.bf16.f32 "
                 "{%0,%1,%2,%3}, {%4,%5,%6,%7}, {%8,%9}, {%0,%1,%2,%3};"
                 : "+f"(d[0]), "+f"(d[1]), "+f"(d[2]), "+f"(d[3])
                 : "r"(a0), "r"(a1), "r"(a2), "r"(a3), "r"(b0), "r"(b1));
}

// ---------------- init: zero pool/cnt/count/tilestate ----------------
__global__ void init_kernel(float* pool, float* cnt, int* count,
                            unsigned long long* tilestate) {
    int i = blockIdx.x * blockDim.x + threadIdx.x;
    if (i < N_GRAPHS * HID) pool[i] = 0.0f;
    if (i < N_NODES) count[i] = 0;
    if (i < N_GRAPHS) cnt[i] = 0.0f;
    if (i < SCAN_B) tilestate[i] = 0ull;
}

// ---------------- degree histogram over dst ----------------
__global__ void hist_kernel(const int* __restrict__ dst, int* __restrict__ count) {
    int t = blockIdx.x * blockDim.x + threadIdx.x;
    if (t >= N_EDGES / 4) return;
    int4 d = __ldg((const int4*)dst + t);
    atomicAdd(&count[d.x], 1);
    atomicAdd(&count[d.y], 1);
    atomicAdd(&count[d.z], 1);
    atomicAdd(&count[d.w], 1);
}

// ---------------- fused single-pass scan (decoupled lookback) + dinv ----------------
__global__ __launch_bounds__(SCAN_T) void scan_fused_kernel(
    const int* __restrict__ count, float* __restrict__ dinv,
    int* __restrict__ rowptr, int* __restrict__ cursor,
    unsigned long long* __restrict__ tilestate)
{
    __shared__ int warptot[SCAN_T / 32];
    __shared__ int s_base;
    const int bid = blockIdx.x;
    const int tid = threadIdx.x;
    int i = bid * SCAN_T + tid;
    int v = (i < N_NODES) ? count[i] : 0;
    if (i < N_NODES) dinv[i] = rsqrtf((float)v + 1.0f);

    // block-wide inclusive scan
    int lane = tid & 31, w = tid >> 5;
    int x = v;
#pragma unroll
    for (int off = 1; off < 32; off <<= 1) {
        int y = __shfl_up_sync(0xffffffffu, x, off);
        if (lane >= off) x += y;
    }
    if (lane == 31) warptot[w] = x;
    __syncthreads();
    if (tid < SCAN_T / 32) {
        int s = warptot[tid];
#pragma unroll
        for (int off = 1; off < SCAN_T / 32; off <<= 1) {
            int y = __shfl_up_sync(0xffu, s, off);
            if ((int)tid >= off) s += y;
        }
        warptot[tid] = s;
    }
    __syncthreads();
    int local_excl = x - v + (w > 0 ? warptot[w - 1] : 0);
    int S = warptot[SCAN_T / 32 - 1];   // block total

    // publish aggregate (tile 0 publishes prefix immediately)
    if (tid == 0) {
        unsigned long long pk = (bid == 0)
            ? ((2ull << 32) | (unsigned int)S)
            : ((1ull << 32) | (unsigned int)S);
        atomicExch(&tilestate[bid], pk);
        if (bid == 0) s_base = 0;
    }

    // warp 0: decoupled lookback (windowed, warp-parallel)
    if (bid > 0 && w == 0) {
        int base = 0;
        int j = bid - 1;
        while (true) {
            int k = j - lane;   // lane 0 reads nearest predecessor
            unsigned long long pk;
            int st, val;
            // re-read window until every in-range lane sees a valid state
            do {
                pk = (k >= 0) ? *((volatile unsigned long long*)&tilestate[k]) : (2ull << 32);
                st = (int)(pk >> 32);
                val = (int)(unsigned int)pk;
            } while (__any_sync(0xffffffffu, st == 0));
            // lowest lane with a prefix (nearest predecessor with full prefix)
            unsigned pm = __ballot_sync(0xffffffffu, st == 2);
            if (pm) {
                int L = __ffs(pm) - 1;   // lanes < L hold aggregates after the prefix
                int contrib = (lane < L) ? val : (lane == L ? val : 0);
#pragma unroll
                for (int off = 16; off > 0; off >>= 1)
                    contrib += __shfl_down_sync(0xffffffffu, contrib, off);
                base += __shfl_sync(0xffffffffu, contrib, 0);
                break;
            } else {
                int contrib = val;
#pragma unroll
                for (int off = 16; off > 0; off >>= 1)
                    contrib += __shfl_down_sync(0xffffffffu, contrib, off);
                base += __shfl_sync(0xffffffffu, contrib, 0);
                j -= 32;
            }
        }
        if (lane == 0) {
            s_base = base;
            atomicExch(&tilestate[bid], (2ull << 32) | (unsigned int)(base + S));
        }
    }
    __syncthreads();

    int excl = s_base + local_excl;
    if (i < N_NODES) {
        rowptr[i] = excl;
        cursor[i] = excl;
    }
    if (i == 0) rowptr[N_NODES] = N_EDGES;
}

// ---------------- fill CSR (packed int2) ----------------
__global__ void fill_kernel(const int* __restrict__ src, const int* __restrict__ dst,
                            const float* __restrict__ dinv, int* __restrict__ cursor,
                            int2* __restrict__ csr)
{
    int e = blockIdx.x * blockDim.x + threadIdx.x;
    if (e >= N_EDGES) return;
    int s = __ldg(src + e);
    int d = __ldg(dst + e);
    int p = atomicAdd(&cursor[d], 1);
    float coef = __ldg(dinv + s) * __ldg(dinv + d);
    csr[p] = make_int2(s, __float_as_int(coef));
}

// ---------------- W prep (both layers; blockIdx.y = layer) ----------------
__global__ void wprep_kernel(const float* __restrict__ W1, const float* __restrict__ W2,
                             __nv_bfloat16* __restrict__ wt_hi,
                             __nv_bfloat16* __restrict__ wt_lo)
{
    int i = blockIdx.x * blockDim.x + threadIdx.x;
    if (i >= HID * HID) return;
    int layer = blockIdx.y;
    const float* W = layer ? W2 : W1;
    int n = i & 127, k = i >> 7;
    float v = W[i];
    __nv_bfloat16 h = __float2bfloat16(v);
    __nv_bfloat16 l = __float2bfloat16(v - __bfloat162float(h));
    wt_hi[layer * HID * HID + n * HID + k] = h;
    wt_lo[layer * HID * HID + n * HID + k] = l;
}

// ---------------- warp-MMA GEMM: H(fp16) = X*W (split-bf16, fp32 accum) ----------------
#define AS 132
#define SM_AH 0
#define SM_AL (SM_AH + 128 * AS * 2)
#define SM_BH (SM_AL + 128 * AS * 2)
#define SM_BL (SM_BH + 128 * AS * 2)
#define SM_GEMM_TOTAL (SM_BL + 128 * AS * 2)   // 135168 B

template <bool FP16IN>
__global__ __launch_bounds__(256) void gemm_mma_kernel(
    const void* __restrict__ Xv,
    const __nv_bfloat16* __restrict__ wt_hi,
    const __nv_bfloat16* __restrict__ wt_lo,
    __half* __restrict__ H, int M)
{
    extern __shared__ char smem[];
    const int tid = threadIdx.x;
    const int wid = tid >> 5;
    const int lane = tid & 31;
    const int rowBase = blockIdx.x * 128;

    {
        int row = tid >> 1;
        int half_ = tid & 1;
        int gr = rowBase + row;
        char* ah = smem + SM_AH + row * (AS * 2) + half_ * 128;
        char* al = smem + SM_AL + row * (AS * 2) + half_ * 128;
#pragma unroll
        for (int k4 = 0; k4 < 16; k4++) {
            float4 v;
            if (FP16IN) {
                const __half* xr = (const __half*)Xv + (size_t)gr * HID + half_ * 64;
                if (gr < M) v = ld_half4(xr + k4 * 4);
                else v = make_float4(0.f, 0.f, 0.f, 0.f);
            } else {
                const float4* xr = (const float4*)((const float*)Xv + (size_t)gr * HID) + half_ * 16;
                v = (gr < M) ? __ldg(&xr[k4]) : make_float4(0.f, 0.f, 0.f, 0.f);
            }
            __nv_bfloat16 h0 = __float2bfloat16(v.x), h1 = __float2bfloat16(v.y);
            __nv_bfloat16 h2 = __float2bfloat16(v.z), h3 = __float2bfloat16(v.w);
            __nv_bfloat16 l0 = __float2bfloat16(v.x - __bfloat162float(h0));
            __nv_bfloat16 l1 = __float2bfloat16(v.y - __bfloat162float(h1));
            __nv_bfloat16 l2 = __float2bfloat16(v.z - __bfloat162float(h2));
            __nv_bfloat16 l3 = __float2bfloat16(v.w - __bfloat162float(h3));
            uint2 hp, lp;
            hp.x = (uint32_t)__bfloat16_as_ushort(h0) | ((uint32_t)__bfloat16_as_ushort(h1) << 16);
            hp.y = (uint32_t)__bfloat16_as_ushort(h2) | ((uint32_t)__bfloat16_as_ushort(h3) << 16);
            lp.x = (uint32_t)__bfloat16_as_ushort(l0) | ((uint32_t)__bfloat16_as_ushort(l1) << 16);
            lp.y = (uint32_t)__bfloat16_as_ushort(l2) | ((uint32_t)__bfloat16_as_ushort(l3) << 16);
            *(uint2*)(ah + k4 * 8) = hp;
            *(uint2*)(al + k4 * 8) = lp;
        }
    }
    {
        const uint32_t* gh = (const uint32_t*)wt_hi;
        const uint32_t* gl = (const uint32_t*)wt_lo;
#pragma unroll
        for (int w = 0; w < 32; w++) {
            int wi = tid + w * 256;
            int r = wi >> 6, c = wi & 63;
            *(uint32_t*)(smem + SM_BH + r * (AS * 2) + c * 4) = __ldg(&gh[r * 64 + c]);
            *(uint32_t*)(smem + SM_BL + r * (AS * 2) + c * 4) = __ldg(&gl[r * 64 + c]);
        }
    }
    __syncthreads();

    const int g = lane >> 2, t = lane & 3;
    const int mOff = (wid & 3) * 32;
    const int nOff = (wid >> 2) * 64;

    float acc[2][8][4];
#pragma unroll
    for (int i = 0; i < 2; i++)
#pragma unroll
        for (int j = 0; j < 8; j++)
#pragma unroll
            for (int q = 0; q < 4; q++) acc[i][j][q] = 0.0f;

#pragma unroll
    for (int ks = 0; ks < 8; ks++) {
        int k0 = ks * 16;
        uint32_t ah[2][4], al[2][4];
#pragma unroll
        for (int i = 0; i < 2; i++) {
            int r0 = mOff + i * 16 + g;
            const char* pah = smem + SM_AH;
            const char* pal = smem + SM_AL;
            ah[i][0] = *(const uint32_t*)(pah + (r0)     * (AS * 2) + (k0 + t * 2) * 2);
            ah[i][1] = *(const uint32_t*)(pah + (r0 + 8) * (AS * 2) + (k0 + t * 2) * 2);
            ah[i][2] = *(const uint32_t*)(pah + (r0)     * (AS * 2) + (k0 + t * 2 + 8) * 2);
            ah[i][3] = *(const uint32_t*)(pah + (r0 + 8) * (AS * 2) + (k0 + t * 2 + 8) * 2);
            al[i][0] = *(const uint32_t*)(pal + (r0)     * (AS * 2) + (k0 + t * 2) * 2);
            al[i][1] = *(const uint32_t*)(pal + (r0 + 8) * (AS * 2) + (k0 + t * 2) * 2);
            al[i][2] = *(const uint32_t*)(pal + (r0)     * (AS * 2) + (k0 + t * 2 + 8) * 2);
            al[i][3] = *(const uint32_t*)(pal + (r0 + 8) * (AS * 2) + (k0 + t * 2 + 8) * 2);
        }
#pragma unroll
        for (int j = 0; j < 8; j++) {
            int n0 = nOff + j * 8 + g;
            uint32_t bh0 = *(const uint32_t*)(smem + SM_BH + n0 * (AS * 2) + (k0 + t * 2) * 2);
            uint32_t bh1 = *(const uint32_t*)(smem + SM_BH + n0 * (AS * 2) + (k0 + t * 2 + 8) * 2);
            uint32_t bl0 = *(const uint32_t*)(smem + SM_BL + n0 * (AS * 2) + (k0 + t * 2) * 2);
            uint32_t bl1 = *(const uint32_t*)(smem + SM_BL + n0 * (AS * 2) + (k0 + t * 2 + 8) * 2);
#pragma unroll
            for (int i = 0; i < 2; i++) {
                mma_bf16(acc[i][j], ah[i][0], ah[i][1], ah[i][2], ah[i][3], bh0, bh1);
                mma_bf16(acc[i][j], ah[i][0], ah[i][1], ah[i][2], ah[i][3], bl0, bl1);
                mma_bf16(acc[i][j], al[i][0], al[i][1], al[i][2], al[i][3], bh0, bh1);
            }
        }
    }

#pragma unroll
    for (int i = 0; i < 2; i++) {
#pragma unroll
        for (int j = 0; j < 8; j++) {
            int row = rowBase + mOff + i * 16 + g;
            int col = nOff + j * 8 + t * 2;
            if (row < M)
                *(__half2*)(H + (size_t)row * HID + col) =
                    __floats2half2_rn(acc[i][j][0], acc[i][j][1]);
            if (row + 8 < M)
                *(__half2*)(H + (size_t)(row + 8) * HID + col) =
                    __floats2half2_rn(acc[i][j][2], acc[i][j][3]);
        }
    }
}

// ---------------- gather core (fp16 H) ----------------
__device__ __forceinline__ float4 gather_node(
    const __half* __restrict__ H, const int* __restrict__ rowptr,
    const int2* __restrict__ csr, const float* __restrict__ dinv,
    const float* __restrict__ bias, int n, int lane)
{
    float di = __ldg(dinv + n);
    float sl = di * di;
    float4 a = ld_half4(H + (size_t)n * HID + lane * 4);
    float4 acc = make_float4(a.x * sl, a.y * sl, a.z * sl, a.w * sl);

    int i   = __ldg(rowptr + n);
    int end = __ldg(rowptr + n + 1);

    for (; i + 4 <= end; i += 4) {
        int2 e0 = __ldg(csr + i + 0);
        int2 e1 = __ldg(csr + i + 1);
        int2 e2 = __ldg(csr + i + 2);
        int2 e3 = __ldg(csr + i + 3);
        float c0 = __int_as_float(e0.y), c1 = __int_as_float(e1.y);
        float c2 = __int_as_float(e2.y), c3 = __int_as_float(e3.y);
        float4 v0 = ld_half4(H + (size_t)e0.x * HID + lane * 4);
        float4 v1 = ld_half4(H + (size_t)e1.x * HID + lane * 4);
        float4 v2 = ld_half4(H + (size_t)e2.x * HID + lane * 4);
        float4 v3 = ld_half4(H + (size_t)e3.x * HID + lane * 4);
        acc.x = fmaf(c0, v0.x, acc.x); acc.y = fmaf(c0, v0.y, acc.y);
        acc.z = fmaf(c0, v0.z, acc.z); acc.w = fmaf(c0, v0.w, acc.w);
        acc.x = fmaf(c1, v1.x, acc.x); acc.y = fmaf(c1, v1.y, acc.y);
        acc.z = fmaf(c1, v1.z, acc.z); acc.w = fmaf(c1, v1.w, acc.w);
        acc.x = fmaf(c2, v2.x, acc.x); acc.y = fmaf(c2, v2.y, acc.y);
        acc.z = fmaf(c2, v2.z, acc.z); acc.w = fmaf(c2, v2.w, acc.w);
        acc.x = fmaf(c3, v3.x, acc.x); acc.y = fmaf(c3, v3.y, acc.y);
        acc.z = fmaf(c3, v3.z, acc.z); acc.w = fmaf(c3, v3.w, acc.w);
    }
    for (; i < end; i++) {
        int2 e = __ldg(csr + i);
        float c = __int_as_float(e.y);
        float4 v = ld_half4(H + (size_t)e.x * HID + lane * 4);
        acc.x = fmaf(c, v.x, acc.x); acc.y = fmaf(c, v.y, acc.y);
        acc.z = fmaf(c, v.z, acc.z); acc.w = fmaf(c, v.w, acc.w);
    }

    float4 b = *(const float4*)(bias + lane * 4);
    acc.x = leaky(acc.x + b.x);
    acc.y = leaky(acc.y + b.y);
    acc.z = leaky(acc.z + b.z);
    acc.w = leaky(acc.w + b.w);
    return acc;
}

// layer-1 gather: write activated fp16 features
__global__ __launch_bounds__(256) void gather_kernel(
    const __half* __restrict__ H, __half* __restrict__ OUT,
    const int* __restrict__ rowptr, const int2* __restrict__ csr,
    const float* __restrict__ dinv, const float* __restrict__ bias)
{
    int n = blockIdx.x * 8 + (threadIdx.x >> 5);
    int lane = threadIdx.x & 31;
    if (n >= N_NODES) return;
    float4 acc = gather_node(H, rowptr, csr, dinv, bias, n, lane);
    __half2 o0 = __floats2half2_rn(acc.x, acc.y);
    __half2 o1 = __floats2half2_rn(acc.z, acc.w);
    uint2 u;
    u.x = *reinterpret_cast<uint32_t*>(&o0);
    u.y = *reinterpret_cast<uint32_t*>(&o1);
    *(uint2*)(OUT + (size_t)n * HID + lane * 4) = u;
}

// layer-2 gather fused with mean-pool accumulation
__global__ __launch_bounds__(256) void gather_pool_kernel(
    const __half* __restrict__ H,
    const int* __restrict__ rowptr, const int2* __restrict__ csr,
    const float* __restrict__ dinv, const float* __restrict__ bias,
    const int* __restrict__ batch, float* __restrict__ pool, float* __restrict__ cnt)
{
    int n = blockIdx.x * 8 + (threadIdx.x >> 5);
    int lane = threadIdx.x & 31;
    if (n >= N_NODES) return;
    float4 acc = gather_node(H, rowptr, csr, dinv, bias, n, lane);
    int g = __ldg(batch + n);
    red_add_v4(pool + (size_t)g * HID + lane * 4, acc.x, acc.y, acc.z, acc.w);
    if (lane == 0) atomicAdd(&cnt[g], 1.0f);
}

// ---------------- finalize ----------------
__global__ void finalize_kernel(const float* __restrict__ pool, const float* __restrict__ cnt,
                                float* __restrict__ out)
{
    int i = blockIdx.x * blockDim.x + threadIdx.x;
    if (i >= N_GRAPHS * HID) return;
    int g = i >> 7;
    out[i] = pool[i] / fmaxf(cnt[g], 1.0f);
}

// ---------------- launch ----------------
extern "C" void kernel_launch(void* const* d_in, const int* in_sizes, int n_in,
                              void* d_out, int out_size)
{
    const float* drug_x = (const float*)d_in[0];
    const float* W1     = (const float*)d_in[1];
    const float* b1     = (const float*)d_in[2];
    const float* W2     = (const float*)d_in[3];
    const float* b2     = (const float*)d_in[4];
    const int*   eidx   = (const int*)d_in[5];
    const int*   batch  = (const int*)d_in[6];
    float* out = (float*)d_out;

    const int* src = eidx;
    const int* dst = eidx + N_EDGES;

    __half *bufH, *bufC;
    float *dinv, *pool, *cnt;
    int *count, *rowptr, *cursor;
    int2* csr;
    unsigned long long* tilestate;
    __nv_bfloat16 *wth, *wtl;
    cudaGetSymbolAddress((void**)&bufH, g_bufH);
    cudaGetSymbolAddress((void**)&bufC, g_bufC);
    cudaGetSymbolAddress((void**)&dinv, g_dinv);
    cudaGetSymbolAddress((void**)&pool, g_pool);
    cudaGetSymbolAddress((void**)&cnt,  g_cnt);
    cudaGetSymbolAddress((void**)&count,  g_count);
    cudaGetSymbolAddress((void**)&rowptr, g_rowptr);
    cudaGetSymbolAddress((void**)&cursor, g_cursor);
    cudaGetSymbolAddress((void**)&csr, g_csr);
    cudaGetSymbolAddress((void**)&tilestate, g_tilestate);
    cudaGetSymbolAddress((void**)&wth, g_wt_hi);
    cudaGetSymbolAddress((void**)&wtl, g_wt_lo);

    cudaFuncSetAttribute(gemm_mma_kernel<false>, cudaFuncAttributeMaxDynamicSharedMemorySize,
                         SM_GEMM_TOTAL);
    cudaFuncSetAttribute(gemm_mma_kernel<true>, cudaFuncAttributeMaxDynamicSharedMemorySize,
                         SM_GEMM_TOTAL);

    const int T = 256;
    int gemm_blocks = (N_NODES + 127) / 128;   // 391
    int gath_blocks = (N_NODES + 7) / 8;

    // CSR build + W prep
    init_kernel<<<(N_GRAPHS * HID + T - 1) / T, T>>>(pool, cnt, count, tilestate);
    {
        dim3 wgrid((HID * HID + T - 1) / T, 2);
        wprep_kernel<<<wgrid, T>>>(W1, W2, wth, wtl);
    }
    hist_kernel<<<(N_EDGES / 4 + T - 1) / T, T>>>(dst, count);
    scan_fused_kernel<<<SCAN_B, SCAN_T>>>(count, dinv, rowptr, cursor, tilestate);
    fill_kernel<<<(N_EDGES + T - 1) / T, T>>>(src, dst, dinv, cursor, csr);

    // layer 1
    gemm_mma_kernel<false><<<gemm_blocks, T, SM_GEMM_TOTAL>>>(drug_x, wth, wtl, bufH, N_NODES);
    gather_kernel<<<gath_blocks, T>>>(bufH, bufC, rowptr, csr, dinv, b1);

    // layer 2 (fp16 input; gather fused with mean-pool)
    gemm_mma_kernel<true><<<gemm_blocks, T, SM_GEMM_TOTAL>>>(bufC, wth + HID * HID, wtl + HID * HID,
                                                             bufH, N_NODES);
    gather_pool_kernel<<<gath_blocks, T>>>(bufH, rowptr, csr, dinv, b2, batch, pool, cnt);

    finalize_kernel<<<(N_GRAPHS * HID + T - 1) / T, T>>>(pool, cnt, out);
}

// round 10
// speedup vs baseline: 2.2788x; 1.0560x over previous
#include <cuda_runtime.h>
#include <cuda_bf16.h>
#include <cuda_fp16.h>
#include <cstdint>

#define N_NODES 50000
#define N_EDGES 600000
#define N_GRAPHS 1000
#define HID 128
#define NEG_SLOPE 0.01f

// scan: 16 nodes/thread, 256 threads -> 4096/block -> 13 blocks (1-window lookback)
#define SCH 16
#define SCAN_T 256
#define SCAN_TILE (SCAN_T * SCH)
#define SCAN_B ((N_NODES + SCAN_TILE - 1) / SCAN_TILE)   // 13

// ---------------- scratch (static device globals; no allocation) ----------------
__device__ __half g_bufH[(size_t)N_NODES * HID];   // GEMM output, fp16
__device__ __half g_bufC[(size_t)N_NODES * HID];   // layer-1 activated output, fp16
__device__ float  g_dinv[N_NODES];
__device__ float  g_pool[N_GRAPHS * HID];
__device__ float  g_cnt[N_GRAPHS];
__device__ int    g_count[N_NODES];
__device__ int    g_rowptr[N_NODES + 1];
__device__ int    g_cursor[N_NODES];
__device__ int2   g_csr[N_EDGES];                  // {src, coef-as-int}
__device__ unsigned long long g_tilestate[32];     // (state<<32)|value; 0=inv,1=agg,2=prefix
// W^T bf16 hi/lo images [N=128][K=128] row-major (both layers)
__device__ __nv_bfloat16 g_wt_hi[2][HID * HID];
__device__ __nv_bfloat16 g_wt_lo[2][HID * HID];

// ---------------- helpers ----------------
__device__ __forceinline__ float leaky(float x) {
    return x > 0.0f ? x : NEG_SLOPE * x;
}

__device__ __forceinline__ void red_add_v4(float* addr, float a, float b, float c, float d) {
    asm volatile("red.global.add.v4.f32 [%0], {%1, %2, %3, %4};"
                 :: "l"(addr), "f"(a), "f"(b), "f"(c), "f"(d) : "memory");
}

__device__ __forceinline__ float4 ld_half4(const __half* p) {
    uint2 u = __ldg((const uint2*)p);
    __half2 h0 = *reinterpret_cast<__half2*>(&u.x);
    __half2 h1 = *reinterpret_cast<__half2*>(&u.y);
    float2 f0 = __half22float2(h0);
    float2 f1 = __half22float2(h1);
    return make_float4(f0.x, f0.y, f1.x, f1.y);
}

__device__ __forceinline__ void mma_bf16(float* d,
                                         uint32_t a0, uint32_t a1, uint32_t a2, uint32_t a3,
                                         uint32_t b0, uint32_t b1) {
    asm volatile("mma.sync.aligned.m16n8k16.row.col.f32.bf16.bf16.f32 "
                 "{%0,%1,%2,%3}, {%4,%5,%6,%7}, {%8,%9}, {%0,%1,%2,%3};"
                 : "+f"(d[0]), "+f"(d[1]), "+f"(d[2]), "+f"(d[3])
                 : "r"(a0), "r"(a1), "r"(a2), "r"(a3), "r"(b0), "r"(b1));
}

// ---------------- init: zero pool/cnt/count/tilestate ----------------
__global__ void init_kernel(float* pool, float* cnt, int* count,
                            unsigned long long* tilestate) {
    int i = blockIdx.x * blockDim.x + threadIdx.x;
    if (i < N_GRAPHS * HID) pool[i] = 0.0f;
    if (i < N_NODES) count[i] = 0;
    if (i < N_GRAPHS) cnt[i] = 0.0f;
    if (i < 32) tilestate[i] = 0ull;
}

// ---------------- degree histogram over dst ----------------
__global__ void hist_kernel(const int* __restrict__ dst, int* __restrict__ count) {
    int t = blockIdx.x * blockDim.x + threadIdx.x;
    if (t >= N_EDGES / 4) return;
    int4 d = __ldg((const int4*)dst + t);
    atomicAdd(&count[d.x], 1);
    atomicAdd(&count[d.y], 1);
    atomicAdd(&count[d.z], 1);
    atomicAdd(&count[d.w], 1);
}

// ---------------- fused single-pass scan (1-window lookback) + dinv ----------------
__global__ __launch_bounds__(SCAN_T) void scan_fused_kernel(
    const int* __restrict__ count, float* __restrict__ dinv,
    int* __restrict__ rowptr, int* __restrict__ cursor,
    unsigned long long* __restrict__ tilestate)
{
    __shared__ int warptot[SCAN_T / 32];
    __shared__ int s_base;
    const int bid = blockIdx.x;
    const int tid = threadIdx.x;
    const int base = bid * SCAN_TILE + tid * SCH;

    // per-thread sequential scan over 16 nodes (+ dinv on the fly)
    int pre[SCH];
    int s = 0;
#pragma unroll
    for (int q = 0; q < SCH; q++) {
        int idx = base + q;
        int c = (idx < N_NODES) ? __ldg(count + idx) : 0;
        if (idx < N_NODES) dinv[idx] = rsqrtf((float)c + 1.0f);
        pre[q] = s;
        s += c;
    }

    // block-wide scan of thread totals
    int lane = tid & 31, w = tid >> 5;
    int x = s;
#pragma unroll
    for (int off = 1; off < 32; off <<= 1) {
        int y = __shfl_up_sync(0xffffffffu, x, off);
        if (lane >= off) x += y;
    }
    if (lane == 31) warptot[w] = x;
    __syncthreads();
    if (tid < SCAN_T / 32) {
        int t2 = warptot[tid];
#pragma unroll
        for (int off = 1; off < SCAN_T / 32; off <<= 1) {
            int y = __shfl_up_sync(0xffu, t2, off);
            if ((int)tid >= off) t2 += y;
        }
        warptot[tid] = t2;
    }
    __syncthreads();
    int thread_excl = x - s + (w > 0 ? warptot[w - 1] : 0);
    int S = warptot[SCAN_T / 32 - 1];   // block total

    if (tid == 0) {
        unsigned long long pk = (bid == 0)
            ? ((2ull << 32) | (unsigned int)S)
            : ((1ull << 32) | (unsigned int)S);
        atomicExch(&tilestate[bid], pk);
        if (bid == 0) s_base = 0;
    }

    // lookback: with 13 tiles all predecessors fit in one warp window
    if (bid > 0 && w == 0) {
        int k = bid - 1 - lane;
        unsigned long long pk;
        int st, val;
        do {
            pk = (k >= 0) ? *((volatile unsigned long long*)&tilestate[k]) : (2ull << 32);
            st = (int)(pk >> 32);
            val = (int)(unsigned int)pk;
        } while (__any_sync(0xffffffffu, st == 0) || !__ballot_sync(0xffffffffu, st == 2));
        unsigned pm = __ballot_sync(0xffffffffu, st == 2);
        int L = __ffs(pm) - 1;
        int contrib = (lane <= L) ? val : 0;
#pragma unroll
        for (int off = 16; off > 0; off >>= 1)
            contrib += __shfl_down_sync(0xffffffffu, contrib, off);
        int base2 = __shfl_sync(0xffffffffu, contrib, 0);
        if (lane == 0) {
            s_base = base2;
            atomicExch(&tilestate[bid], (2ull << 32) | (unsigned int)(base2 + S));
        }
    }
    __syncthreads();

    int excl0 = s_base + thread_excl;
#pragma unroll
    for (int q = 0; q < SCH; q++) {
        int idx = base + q;
        if (idx < N_NODES) {
            rowptr[idx] = excl0 + pre[q];
            cursor[idx] = excl0 + pre[q];
        }
    }
    if (bid == 0 && tid == 0) rowptr[N_NODES] = N_EDGES;
}

// ---------------- fill CSR (packed int2) ----------------
__global__ void fill_kernel(const int* __restrict__ src, const int* __restrict__ dst,
                            const float* __restrict__ dinv, int* __restrict__ cursor,
                            int2* __restrict__ csr)
{
    int e = blockIdx.x * blockDim.x + threadIdx.x;
    if (e >= N_EDGES) return;
    int s = __ldg(src + e);
    int d = __ldg(dst + e);
    int p = atomicAdd(&cursor[d], 1);
    float coef = __ldg(dinv + s) * __ldg(dinv + d);
    csr[p] = make_int2(s, __float_as_int(coef));
}

// ---------------- W prep (both layers; blockIdx.y = layer) ----------------
__global__ void wprep_kernel(const float* __restrict__ W1, const float* __restrict__ W2,
                             __nv_bfloat16* __restrict__ wt_hi,
                             __nv_bfloat16* __restrict__ wt_lo)
{
    int i = blockIdx.x * blockDim.x + threadIdx.x;
    if (i >= HID * HID) return;
    int layer = blockIdx.y;
    const float* W = layer ? W2 : W1;
    int n = i & 127, k = i >> 7;
    float v = W[i];
    __nv_bfloat16 h = __float2bfloat16(v);
    __nv_bfloat16 l = __float2bfloat16(v - __bfloat162float(h));
    wt_hi[layer * HID * HID + n * HID + k] = h;
    wt_lo[layer * HID * HID + n * HID + k] = l;
}

// ---------------- warp-MMA GEMM: H(fp16) = X*W (split-bf16, fp32 accum) ----------------
#define AS 132
#define SM_AH 0
#define SM_AL (SM_AH + 128 * AS * 2)
#define SM_BH (SM_AL + 128 * AS * 2)
#define SM_BL (SM_BH + 128 * AS * 2)
#define SM_GEMM_TOTAL (SM_BL + 128 * AS * 2)   // 135168 B

template <bool FP16IN>
__global__ __launch_bounds__(256) void gemm_mma_kernel(
    const void* __restrict__ Xv,
    const __nv_bfloat16* __restrict__ wt_hi,
    const __nv_bfloat16* __restrict__ wt_lo,
    __half* __restrict__ H, int M)
{
    extern __shared__ char smem[];
    const int tid = threadIdx.x;
    const int wid = tid >> 5;
    const int lane = tid & 31;
    const int rowBase = blockIdx.x * 128;

    {
        int row = tid >> 1;
        int half_ = tid & 1;
        int gr = rowBase + row;
        char* ah = smem + SM_AH + row * (AS * 2) + half_ * 128;
        char* al = smem + SM_AL + row * (AS * 2) + half_ * 128;
#pragma unroll
        for (int k4 = 0; k4 < 16; k4++) {
            float4 v;
            if (FP16IN) {
                const __half* xr = (const __half*)Xv + (size_t)gr * HID + half_ * 64;
                if (gr < M) v = ld_half4(xr + k4 * 4);
                else v = make_float4(0.f, 0.f, 0.f, 0.f);
            } else {
                const float4* xr = (const float4*)((const float*)Xv + (size_t)gr * HID) + half_ * 16;
                v = (gr < M) ? __ldg(&xr[k4]) : make_float4(0.f, 0.f, 0.f, 0.f);
            }
            __nv_bfloat16 h0 = __float2bfloat16(v.x), h1 = __float2bfloat16(v.y);
            __nv_bfloat16 h2 = __float2bfloat16(v.z), h3 = __float2bfloat16(v.w);
            __nv_bfloat16 l0 = __float2bfloat16(v.x - __bfloat162float(h0));
            __nv_bfloat16 l1 = __float2bfloat16(v.y - __bfloat162float(h1));
            __nv_bfloat16 l2 = __float2bfloat16(v.z - __bfloat162float(h2));
            __nv_bfloat16 l3 = __float2bfloat16(v.w - __bfloat162float(h3));
            uint2 hp, lp;
            hp.x = (uint32_t)__bfloat16_as_ushort(h0) | ((uint32_t)__bfloat16_as_ushort(h1) << 16);
            hp.y = (uint32_t)__bfloat16_as_ushort(h2) | ((uint32_t)__bfloat16_as_ushort(h3) << 16);
            lp.x = (uint32_t)__bfloat16_as_ushort(l0) | ((uint32_t)__bfloat16_as_ushort(l1) << 16);
            lp.y = (uint32_t)__bfloat16_as_ushort(l2) | ((uint32_t)__bfloat16_as_ushort(l3) << 16);
            *(uint2*)(ah + k4 * 8) = hp;
            *(uint2*)(al + k4 * 8) = lp;
        }
    }
    {
        const uint32_t* gh = (const uint32_t*)wt_hi;
        const uint32_t* gl = (const uint32_t*)wt_lo;
#pragma unroll
        for (int w = 0; w < 32; w++) {
            int wi = tid + w * 256;
            int r = wi >> 6, c = wi & 63;
            *(uint32_t*)(smem + SM_BH + r * (AS * 2) + c * 4) = __ldg(&gh[r * 64 + c]);
            *(uint32_t*)(smem + SM_BL + r * (AS * 2) + c * 4) = __ldg(&gl[r * 64 + c]);
        }
    }
    __syncthreads();

    const int g = lane >> 2, t = lane & 3;
    const int mOff = (wid & 3) * 32;
    const int nOff = (wid >> 2) * 64;

    float acc[2][8][4];
#pragma unroll
    for (int i = 0; i < 2; i++)
#pragma unroll
        for (int j = 0; j < 8; j++)
#pragma unroll
            for (int q = 0; q < 4; q++) acc[i][j][q] = 0.0f;

#pragma unroll
    for (int ks = 0; ks < 8; ks++) {
        int k0 = ks * 16;
        uint32_t ah[2][4], al[2][4];
#pragma unroll
        for (int i = 0; i < 2; i++) {
            int r0 = mOff + i * 16 + g;
            const char* pah = smem + SM_AH;
            const char* pal = smem + SM_AL;
            ah[i][0] = *(const uint32_t*)(pah + (r0)     * (AS * 2) + (k0 + t * 2) * 2);
            ah[i][1] = *(const uint32_t*)(pah + (r0 + 8) * (AS * 2) + (k0 + t * 2) * 2);
            ah[i][2] = *(const uint32_t*)(pah + (r0)     * (AS * 2) + (k0 + t * 2 + 8) * 2);
            ah[i][3] = *(const uint32_t*)(pah + (r0 + 8) * (AS * 2) + (k0 + t * 2 + 8) * 2);
            al[i][0] = *(const uint32_t*)(pal + (r0)     * (AS * 2) + (k0 + t * 2) * 2);
            al[i][1] = *(const uint32_t*)(pal + (r0 + 8) * (AS * 2) + (k0 + t * 2) * 2);
            al[i][2] = *(const uint32_t*)(pal + (r0)     * (AS * 2) + (k0 + t * 2 + 8) * 2);
            al[i][3] = *(const uint32_t*)(pal + (r0 + 8) * (AS * 2) + (k0 + t * 2 + 8) * 2);
        }
#pragma unroll
        for (int j = 0; j < 8; j++) {
            int n0 = nOff + j * 8 + g;
            uint32_t bh0 = *(const uint32_t*)(smem + SM_BH + n0 * (AS * 2) + (k0 + t * 2) * 2);
            uint32_t bh1 = *(const uint32_t*)(smem + SM_BH + n0 * (AS * 2) + (k0 + t * 2 + 8) * 2);
            uint32_t bl0 = *(const uint32_t*)(smem + SM_BL + n0 * (AS * 2) + (k0 + t * 2) * 2);
            uint32_t bl1 = *(const uint32_t*)(smem + SM_BL + n0 * (AS * 2) + (k0 + t * 2 + 8) * 2);
#pragma unroll
            for (int i = 0; i < 2; i++) {
                mma_bf16(acc[i][j], ah[i][0], ah[i][1], ah[i][2], ah[i][3], bh0, bh1);
                mma_bf16(acc[i][j], ah[i][0], ah[i][1], ah[i][2], ah[i][3], bl0, bl1);
                mma_bf16(acc[i][j], al[i][0], al[i][1], al[i][2], al[i][3], bh0, bh1);
            }
        }
    }

#pragma unroll
    for (int i = 0; i < 2; i++) {
#pragma unroll
        for (int j = 0; j < 8; j++) {
            int row = rowBase + mOff + i * 16 + g;
            int col = nOff + j * 8 + t * 2;
            if (row < M)
                *(__half2*)(H + (size_t)row * HID + col) =
                    __floats2half2_rn(acc[i][j][0], acc[i][j][1]);
            if (row + 8 < M)
                *(__half2*)(H + (size_t)(row + 8) * HID + col) =
                    __floats2half2_rn(acc[i][j][2], acc[i][j][3]);
        }
    }
}

// ---------------- gather core (fp16 H) ----------------
__device__ __forceinline__ float4 gather_node(
    const __half* __restrict__ H, const int* __restrict__ rowptr,
    const int2* __restrict__ csr, const float* __restrict__ dinv,
    const float* __restrict__ bias, int n, int lane)
{
    float di = __ldg(dinv + n);
    float sl = di * di;
    float4 a = ld_half4(H + (size_t)n * HID + lane * 4);
    float4 acc = make_float4(a.x * sl, a.y * sl, a.z * sl, a.w * sl);

    int i   = __ldg(rowptr + n);
    int end = __ldg(rowptr + n + 1);

    for (; i + 4 <= end; i += 4) {
        int2 e0 = __ldg(csr + i + 0);
        int2 e1 = __ldg(csr + i + 1);
        int2 e2 = __ldg(csr + i + 2);
        int2 e3 = __ldg(csr + i + 3);
        float c0 = __int_as_float(e0.y), c1 = __int_as_float(e1.y);
        float c2 = __int_as_float(e2.y), c3 = __int_as_float(e3.y);
        float4 v0 = ld_half4(H + (size_t)e0.x * HID + lane * 4);
        float4 v1 = ld_half4(H + (size_t)e1.x * HID + lane * 4);
        float4 v2 = ld_half4(H + (size_t)e2.x * HID + lane * 4);
        float4 v3 = ld_half4(H + (size_t)e3.x * HID + lane * 4);
        acc.x = fmaf(c0, v0.x, acc.x); acc.y = fmaf(c0, v0.y, acc.y);
        acc.z = fmaf(c0, v0.z, acc.z); acc.w = fmaf(c0, v0.w, acc.w);
        acc.x = fmaf(c1, v1.x, acc.x); acc.y = fmaf(c1, v1.y, acc.y);
        acc.z = fmaf(c1, v1.z, acc.z); acc.w = fmaf(c1, v1.w, acc.w);
        acc.x = fmaf(c2, v2.x, acc.x); acc.y = fmaf(c2, v2.y, acc.y);
        acc.z = fmaf(c2, v2.z, acc.z); acc.w = fmaf(c2, v2.w, acc.w);
        acc.x = fmaf(c3, v3.x, acc.x); acc.y = fmaf(c3, v3.y, acc.y);
        acc.z = fmaf(c3, v3.z, acc.z); acc.w = fmaf(c3, v3.w, acc.w);
    }
    for (; i < end; i++) {
        int2 e = __ldg(csr + i);
        float c = __int_as_float(e.y);
        float4 v = ld_half4(H + (size_t)e.x * HID + lane * 4);
        acc.x = fmaf(c, v.x, acc.x); acc.y = fmaf(c, v.y, acc.y);
        acc.z = fmaf(c, v.z, acc.z); acc.w = fmaf(c, v.w, acc.w);
    }

    float4 b = *(const float4*)(bias + lane * 4);
    acc.x = leaky(acc.x + b.x);
    acc.y = leaky(acc.y + b.y);
    acc.z = leaky(acc.z + b.z);
    acc.w = leaky(acc.w + b.w);
    return acc;
}

// layer-1 gather: write activated fp16 features
__global__ __launch_bounds__(256) void gather_kernel(
    const __half* __restrict__ H, __half* __restrict__ OUT,
    const int* __restrict__ rowptr, const int2* __restrict__ csr,
    const float* __restrict__ dinv, const float* __restrict__ bias)
{
    int n = blockIdx.x * 8 + (threadIdx.x >> 5);
    int lane = threadIdx.x & 31;
    if (n >= N_NODES) return;
    float4 acc = gather_node(H, rowptr, csr, dinv, bias, n, lane);
    __half2 o0 = __floats2half2_rn(acc.x, acc.y);
    __half2 o1 = __floats2half2_rn(acc.z, acc.w);
    uint2 u;
    u.x = *reinterpret_cast<uint32_t*>(&o0);
    u.y = *reinterpret_cast<uint32_t*>(&o1);
    *(uint2*)(OUT + (size_t)n * HID + lane * 4) = u;
}

// layer-2 gather fused with mean-pool accumulation
__global__ __launch_bounds__(256) void gather_pool_kernel(
    const __half* __restrict__ H,
    const int* __restrict__ rowptr, const int2* __restrict__ csr,
    const float* __restrict__ dinv, const float* __restrict__ bias,
    const int* __restrict__ batch, float* __restrict__ pool, float* __restrict__ cnt)
{
    int n = blockIdx.x * 8 + (threadIdx.x >> 5);
    int lane = threadIdx.x & 31;
    if (n >= N_NODES) return;
    float4 acc = gather_node(H, rowptr, csr, dinv, bias, n, lane);
    int g = __ldg(batch + n);
    red_add_v4(pool + (size_t)g * HID + lane * 4, acc.x, acc.y, acc.z, acc.w);
    if (lane == 0) atomicAdd(&cnt[g], 1.0f);
}

// ---------------- finalize ----------------
__global__ void finalize_kernel(const float* __restrict__ pool, const float* __restrict__ cnt,
                                float* __restrict__ out)
{
    int i = blockIdx.x * blockDim.x + threadIdx.x;
    if (i >= N_GRAPHS * HID) return;
    int g = i >> 7;
    out[i] = pool[i] / fmaxf(cnt[g], 1.0f);
}

// ---------------- launch ----------------
extern "C" void kernel_launch(void* const* d_in, const int* in_sizes, int n_in,
                              void* d_out, int out_size)
{
    const float* drug_x = (const float*)d_in[0];
    const float* W1     = (const float*)d_in[1];
    const float* b1     = (const float*)d_in[2];
    const float* W2     = (const float*)d_in[3];
    const float* b2     = (const float*)d_in[4];
    const int*   eidx   = (const int*)d_in[5];
    const int*   batch  = (const int*)d_in[6];
    float* out = (float*)d_out;

    const int* src = eidx;
    const int* dst = eidx + N_EDGES;

    __half *bufH, *bufC;
    float *dinv, *pool, *cnt;
    int *count, *rowptr, *cursor;
    int2* csr;
    unsigned long long* tilestate;
    __nv_bfloat16 *wth, *wtl;
    cudaGetSymbolAddress((void**)&bufH, g_bufH);
    cudaGetSymbolAddress((void**)&bufC, g_bufC);
    cudaGetSymbolAddress((void**)&dinv, g_dinv);
    cudaGetSymbolAddress((void**)&pool, g_pool);
    cudaGetSymbolAddress((void**)&cnt,  g_cnt);
    cudaGetSymbolAddress((void**)&count,  g_count);
    cudaGetSymbolAddress((void**)&rowptr, g_rowptr);
    cudaGetSymbolAddress((void**)&cursor, g_cursor);
    cudaGetSymbolAddress((void**)&csr, g_csr);
    cudaGetSymbolAddress((void**)&tilestate, g_tilestate);
    cudaGetSymbolAddress((void**)&wth, g_wt_hi);
    cudaGetSymbolAddress((void**)&wtl, g_wt_lo);

    // one-time side stream + events (created on first (non-captured) correctness call)
    static cudaStream_t s2 = nullptr;
    static cudaEvent_t evFork = nullptr, evJoin = nullptr;
    if (!s2) {
        cudaStreamCreateWithFlags(&s2, cudaStreamNonBlocking);
        cudaEventCreateWithFlags(&evFork, cudaEventDisableTiming);
        cudaEventCreateWithFlags(&evJoin, cudaEventDisableTiming);
        cudaFuncSetAttribute(gemm_mma_kernel<false>,
                             cudaFuncAttributeMaxDynamicSharedMemorySize, SM_GEMM_TOTAL);
        cudaFuncSetAttribute(gemm_mma_kernel<true>,
                             cudaFuncAttributeMaxDynamicSharedMemorySize, SM_GEMM_TOTAL);
    }

    const int T = 256;
    int gemm_blocks = (N_NODES + 127) / 128;   // 391
    int gath_blocks = (N_NODES + 7) / 8;

    // fork: CSR build chain on s2, wprep+gemm1 on the main (capture) stream
    cudaEventRecord(evFork, 0);
    cudaStreamWaitEvent(s2, evFork, 0);

    // s2 branch: CSR build
    init_kernel<<<(N_GRAPHS * HID + T - 1) / T, T, 0, s2>>>(pool, cnt, count, tilestate);
    hist_kernel<<<(N_EDGES / 4 + T - 1) / T, T, 0, s2>>>(dst, count);
    scan_fused_kernel<<<SCAN_B, SCAN_T, 0, s2>>>(count, dinv, rowptr, cursor, tilestate);
    fill_kernel<<<(N_EDGES + T - 1) / T, T, 0, s2>>>(src, dst, dinv, cursor, csr);
    cudaEventRecord(evJoin, s2);

    // main branch: W prep + layer-1 GEMM (independent of CSR)
    {
        dim3 wgrid((HID * HID + T - 1) / T, 2);
        wprep_kernel<<<wgrid, T>>>(W1, W2, wth, wtl);
    }
    gemm_mma_kernel<false><<<gemm_blocks, T, SM_GEMM_TOTAL>>>(drug_x, wth, wtl, bufH, N_NODES);

    // join: everything below needs both branches
    cudaStreamWaitEvent(0, evJoin, 0);

    gather_kernel<<<gath_blocks, T>>>(bufH, bufC, rowptr, csr, dinv, b1);
    gemm_mma_kernel<true><<<gemm_blocks, T, SM_GEMM_TOTAL>>>(bufC, wth + HID * HID, wtl + HID * HID,
                                                             bufH, N_NODES);
    gather_pool_kernel<<<gath_blocks, T>>>(bufH, rowptr, csr, dinv, b2, batch, pool, cnt);
    finalize_kernel<<<(N_GRAPHS * HID + T - 1) / T, T>>>(pool, cnt, out);
}